// round 12
// baseline (speedup 1.0000x reference)
#include <cuda_runtime.h>
#include <stdint.h>

#define N_NODES 100000
#define N_EDGES 600000
#define D 128
#define H 256
#define TILE_M 64
#define NTILES ((N_NODES + TILE_M - 1) / TILE_M)   // 1563

#define LDX 136   // smem row stride (floats), 128-col tile; 136%32==8 -> conflict-free LDS.64
#define LDH 264   // smem row stride (floats), 256-col tile; 264%32==8

// Scratch (allocation-free rule: device globals)
__device__ float g_m[(size_t)N_NODES * D];
__device__ float g_agg[(size_t)N_NODES * D];

// Pre-packed tf32 weights in mma-fragment order:
//   pW[(kt*Ng + g)*32 + lane] = { tf32(W[kt*8   + lane%4][g*8 + lane/4]),
//                                 tf32(W[kt*8+4 + lane%4][g*8 + lane/4]) }
__device__ uint2 g_pWm1[16 * 32 * 32];
__device__ uint2 g_pWm2[32 * 16 * 32];
__device__ uint2 g_pWn1[32 * 32 * 32];
__device__ uint2 g_pWn2[32 * 16 * 32];

// ---------------------------------------------------------------------------
// helpers
// ---------------------------------------------------------------------------
__device__ __forceinline__ uint32_t f2tf(float f) {
    uint32_t u;
    asm("cvt.rna.tf32.f32 %0, %1;" : "=r"(u) : "f"(f));
    return u;
}

__device__ __forceinline__ void mma_tf32(float c[4], const uint32_t a[4], const uint32_t* b) {
    asm volatile(
        "mma.sync.aligned.m16n8k8.row.col.f32.tf32.tf32.f32 "
        "{%0,%1,%2,%3}, {%4,%5,%6,%7}, {%8,%9}, {%0,%1,%2,%3};\n"
        : "+f"(c[0]), "+f"(c[1]), "+f"(c[2]), "+f"(c[3])
        : "r"(a[0]), "r"(a[1]), "r"(a[2]), "r"(a[3]),
          "r"(b[0]), "r"(b[1]));
}

// Load one A fragment (rows row, row+8; k = kb+lr, kb+lr+4) from permuted smem
// with two LDS.64. Permutation within each 8-col group: pos(k) = (k%4)*2 + k/4,
// so {k, k+4} are adjacent at offset kb + lr*2.
__device__ __forceinline__ void load_afrag(uint32_t a[4], const uint32_t* s,
                                           int row, int ld, int kb, int lr)
{
    uint64_t lo = *reinterpret_cast<const uint64_t*>(s + row * ld + kb + lr * 2);
    uint64_t hi = *reinterpret_cast<const uint64_t*>(s + (row + 8) * ld + kb + lr * 2);
    a[0] = (uint32_t)lo; a[2] = (uint32_t)(lo >> 32);
    a[1] = (uint32_t)hi; a[3] = (uint32_t)(hi >> 32);
}

// ---------------------------------------------------------------------------
// One fused pack kernel: all four weight matrices -> fragment-ordered tf32
// ---------------------------------------------------------------------------
__device__ __forceinline__ void pack_one(const float* __restrict__ W,
                                         uint2* __restrict__ pW,
                                         int id, int Ng, int N)
{
    int lane = id & 31;
    int g    = (id >> 5) % Ng;
    int kt   = (id >> 5) / Ng;
    int lr = lane & 3, lq = lane >> 2;
    int col = g * 8 + lq;
    uint2 v;
    v.x = f2tf(W[(size_t)(kt * 8 + lr)     * N + col]);
    v.y = f2tf(W[(size_t)(kt * 8 + 4 + lr) * N + col]);
    pW[id] = v;
}

__global__ void pack_all_kernel(const float* __restrict__ Wm1, const float* __restrict__ Wm2,
                                const float* __restrict__ Wn1, const float* __restrict__ Wn2)
{
    const int n1 = 16 * 32 * 32;
    const int n2 = 32 * 16 * 32;
    const int n3 = 32 * 32 * 32;
    const int n4 = 32 * 16 * 32;
    int id = blockIdx.x * 256 + threadIdx.x;
    if (id < n1)                     pack_one(Wm1, g_pWm1, id,                32, H);
    else if (id < n1 + n2)           pack_one(Wm2, g_pWm2, id - n1,           16, D);
    else if (id < n1 + n2 + n3)      pack_one(Wn1, g_pWn1, id - n1 - n2,      32, H);
    else if (id < n1 + n2 + n3 + n4) pack_one(Wn2, g_pWn2, id - n1 - n2 - n3, 16, D);
}

// ---------------------------------------------------------------------------
// Kernel 1: m = relu(X @ Wm1 + bm1) @ Wm2 + bm2   + zero g_agg rows
//   64-row tiles, 256 threads (8 warps), 2 CTAs/SM.
// ---------------------------------------------------------------------------
__global__ __launch_bounds__(256, 2)
void msg_mlp_kernel(const float* __restrict__ nodes,
                    const float* __restrict__ bm1, const float* __restrict__ bm2)
{
    extern __shared__ uint32_t smem[];
    uint32_t* sX = smem;                    // [64][LDX] permuted tf32
    uint32_t* sH = smem + TILE_M * LDX;     // [64][LDH] permuted tf32

    const int row0 = blockIdx.x * TILE_M;
    const int tid  = threadIdx.x;
    const int warp = tid >> 5;
    const int lane = tid & 31;
    const int lq   = lane >> 2;
    const int lr   = lane & 3;
    // permuted position of logical col lr*2 within its 8-group (pos(k+1)=pos(k)+2)
    const int p0   = (lr < 2) ? lr * 4 : (lr - 2) * 4 + 1;

    // zero this tile's g_agg rows
    for (int i = tid; i < TILE_M * (D / 4); i += 256) {
        int r  = i >> 5;
        int c4 = (i & 31) * 4;
        int gr = row0 + r;
        if (gr < N_NODES)
            *reinterpret_cast<float4*>(g_agg + (size_t)gr * D + c4) =
                make_float4(0.f, 0.f, 0.f, 0.f);
    }

    // stage X tile (fp32 -> tf32), permuted: group g8 keeps 8 slots, cols c4..c4+3
    // land at positions {0,2,4,6} (c4%8==0) or {1,3,5,7} (c4%8==4)
    for (int i = tid; i < TILE_M * (D / 4); i += 256) {
        int r  = i >> 5;
        int c4 = (i & 31) * 4;
        float4 v = make_float4(0.f, 0.f, 0.f, 0.f);
        int gr = row0 + r;
        if (gr < N_NODES) v = *reinterpret_cast<const float4*>(nodes + (size_t)gr * D + c4);
        uint32_t* dst = sX + r * LDX + (c4 & ~7) + ((c4 & 4) >> 2);
        dst[0] = f2tf(v.x); dst[2] = f2tf(v.y); dst[4] = f2tf(v.z); dst[6] = f2tf(v.w);
    }
    __syncthreads();

    // ---- GEMM1: hidden[64x256] = relu(X @ Wm1 + bm1); warp owns 32 cols
    {
        const int g0 = warp * 4;
        const int KT = D / 8;               // 16
        const int NG = H / 8;               // 32

        float acc[4][4][4];
        #pragma unroll
        for (int i = 0; i < 4; ++i)
            #pragma unroll
            for (int j = 0; j < 4; ++j)
                #pragma unroll
                for (int k = 0; k < 4; ++k) acc[i][j][k] = 0.f;

        uint2 bb[2][4];
        #pragma unroll
        for (int ct = 0; ct < 4; ++ct)
            bb[0][ct] = g_pWm1[(size_t)(g0 + ct) * 32 + lane];

        #pragma unroll 1
        for (int kt = 0; kt < KT; ++kt) {
            const int cur = kt & 1;
            if (kt + 1 < KT) {
                #pragma unroll
                for (int ct = 0; ct < 4; ++ct)
                    bb[cur ^ 1][ct] = g_pWm1[(size_t)((kt + 1) * NG + g0 + ct) * 32 + lane];
            }
            const int kb = kt * 8;
            #pragma unroll
            for (int rt = 0; rt < 4; ++rt) {
                uint32_t a[4];
                load_afrag(a, sX, rt * 16 + lq, LDX, kb, lr);
                #pragma unroll
                for (int ct = 0; ct < 4; ++ct)
                    mma_tf32(acc[rt][ct], a, reinterpret_cast<const uint32_t*>(&bb[cur][ct]));
            }
        }
        // bias + relu -> sH (tf32, permuted)
        #pragma unroll
        for (int rt = 0; rt < 4; ++rt) {
            #pragma unroll
            for (int ct = 0; ct < 4; ++ct) {
                int r = rt * 16 + lq;
                int cbase = warp * 32 + ct * 8;         // group base (logical == physical)
                int c = cbase + lr * 2;                 // logical col for bias
                float b0 = __ldg(bm1 + c), b1 = __ldg(bm1 + c + 1);
                uint32_t* d0 = sH + r * LDH + cbase + p0;
                uint32_t* d1 = sH + (r + 8) * LDH + cbase + p0;
                d0[0] = f2tf(fmaxf(acc[rt][ct][0] + b0, 0.f));
                d0[2] = f2tf(fmaxf(acc[rt][ct][1] + b1, 0.f));
                d1[0] = f2tf(fmaxf(acc[rt][ct][2] + b0, 0.f));
                d1[2] = f2tf(fmaxf(acc[rt][ct][3] + b1, 0.f));
            }
        }
    }
    __syncthreads();

    // ---- GEMM2: m[64x128] = hidden @ Wm2 + bm2
    {
        const int wr = warp >> 2;           // 0..1 -> rows wr*32
        const int wc = warp & 3;            // 0..3 -> cols wc*32
        const int g0 = wc * 4;
        const int KT = H / 8;               // 32
        const int NG = D / 8;               // 16

        float acc[2][4][4];
        #pragma unroll
        for (int i = 0; i < 2; ++i)
            #pragma unroll
            for (int j = 0; j < 4; ++j)
                #pragma unroll
                for (int k = 0; k < 4; ++k) acc[i][j][k] = 0.f;

        uint2 bb[2][4];
        #pragma unroll
        for (int ct = 0; ct < 4; ++ct)
            bb[0][ct] = g_pWm2[(size_t)(g0 + ct) * 32 + lane];

        #pragma unroll 1
        for (int kt = 0; kt < KT; ++kt) {
            const int cur = kt & 1;
            if (kt + 1 < KT) {
                #pragma unroll
                for (int ct = 0; ct < 4; ++ct)
                    bb[cur ^ 1][ct] = g_pWm2[(size_t)((kt + 1) * NG + g0 + ct) * 32 + lane];
            }
            const int kb = kt * 8;
            #pragma unroll
            for (int rt = 0; rt < 2; ++rt) {
                uint32_t a[4];
                load_afrag(a, sH, wr * 32 + rt * 16 + lq, LDH, kb, lr);
                #pragma unroll
                for (int ct = 0; ct < 4; ++ct)
                    mma_tf32(acc[rt][ct], a, reinterpret_cast<const uint32_t*>(&bb[cur][ct]));
            }
        }
        #pragma unroll
        for (int rt = 0; rt < 2; ++rt) {
            #pragma unroll
            for (int ct = 0; ct < 4; ++ct) {
                int r = wr * 32 + rt * 16 + lq;
                int c = wc * 32 + ct * 8 + lr * 2;
                float b0 = __ldg(bm2 + c), b1 = __ldg(bm2 + c + 1);
                int gr = row0 + r;
                if (gr < N_NODES) {
                    float2 v = make_float2(acc[rt][ct][0] + b0, acc[rt][ct][1] + b1);
                    *reinterpret_cast<float2*>(g_m + (size_t)gr * D + c) = v;
                }
                int gr2 = gr + 8;
                if (gr2 < N_NODES) {
                    float2 v = make_float2(acc[rt][ct][2] + b0, acc[rt][ct][3] + b1);
                    *reinterpret_cast<float2*>(g_m + (size_t)gr2 * D + c) = v;
                }
            }
        }
    }
}

// ---------------------------------------------------------------------------
// Kernel 2: agg[recv] += m[send]   (one warp per edge, vector red to L2)
// ---------------------------------------------------------------------------
__global__ __launch_bounds__(256)
void scatter_kernel(const int* __restrict__ senders, const int* __restrict__ receivers)
{
    int e = (blockIdx.x * 256 + threadIdx.x) >> 5;
    int lane = threadIdx.x & 31;
    if (e >= N_EDGES) return;
    int s = __ldg(senders + e);
    int r = __ldg(receivers + e);
    float4 v = *reinterpret_cast<const float4*>(g_m + (size_t)s * D + lane * 4);
    float* dst = g_agg + (size_t)r * D + lane * 4;
    asm volatile("red.global.add.v4.f32 [%0], {%1,%2,%3,%4};"
                 :: "l"(dst), "f"(v.x), "f"(v.y), "f"(v.z), "f"(v.w)
                 : "memory");
}

// ---------------------------------------------------------------------------
// Kernel 3: out = nodes + relu([nodes||agg] @ Wn1 + bn1) @ Wn2 + bn2
//   64-row tiles, 256 threads, 2 CTAs/SM.
// ---------------------------------------------------------------------------
__global__ __launch_bounds__(256, 2)
void node_mlp_kernel(const float* __restrict__ nodes,
                     const float* __restrict__ bn1, const float* __restrict__ bn2,
                     float* __restrict__ out)
{
    extern __shared__ uint32_t smem[];
    uint32_t* sA = smem;   // [64][LDH] permuted; A = [X||agg], later reused as hidden

    const int row0 = blockIdx.x * TILE_M;
    const int tid  = threadIdx.x;
    const int warp = tid >> 5;
    const int lane = tid & 31;
    const int lq   = lane >> 2;
    const int lr   = lane & 3;
    const int p0   = (lr < 2) ? lr * 4 : (lr - 2) * 4 + 1;

    // stage A = [nodes || agg], 64 x 256, tf32, permuted
    for (int i = tid; i < TILE_M * (2 * D / 4); i += 256) {
        int r  = i >> 6;
        int c4 = (i & 63) * 4;
        float4 v = make_float4(0.f, 0.f, 0.f, 0.f);
        int gr = row0 + r;
        if (gr < N_NODES) {
            if (c4 < D) v = *reinterpret_cast<const float4*>(nodes + (size_t)gr * D + c4);
            else        v = *reinterpret_cast<const float4*>(g_agg + (size_t)gr * D + (c4 - D));
        }
        uint32_t* dst = sA + r * LDH + (c4 & ~7) + ((c4 & 4) >> 2);
        dst[0] = f2tf(v.x); dst[2] = f2tf(v.y); dst[4] = f2tf(v.z); dst[6] = f2tf(v.w);
    }
    __syncthreads();

    // ---- GEMM1: hidden[64x256] = relu(A @ Wn1 + bn1); warp owns 32 cols
    float acc1[4][4][4];
    #pragma unroll
    for (int i = 0; i < 4; ++i)
        #pragma unroll
        for (int j = 0; j < 4; ++j)
            #pragma unroll
            for (int k = 0; k < 4; ++k) acc1[i][j][k] = 0.f;

    {
        const int g0 = warp * 4;
        const int KT = (2 * D) / 8;         // 32
        const int NG = H / 8;               // 32

        uint2 bb[2][4];
        #pragma unroll
        for (int ct = 0; ct < 4; ++ct)
            bb[0][ct] = g_pWn1[(size_t)(g0 + ct) * 32 + lane];

        #pragma unroll 1
        for (int kt = 0; kt < KT; ++kt) {
            const int cur = kt & 1;
            if (kt + 1 < KT) {
                #pragma unroll
                for (int ct = 0; ct < 4; ++ct)
                    bb[cur ^ 1][ct] = g_pWn1[(size_t)((kt + 1) * NG + g0 + ct) * 32 + lane];
            }
            const int kb = kt * 8;
            #pragma unroll
            for (int rt = 0; rt < 4; ++rt) {
                uint32_t a[4];
                load_afrag(a, sA, rt * 16 + lq, LDH, kb, lr);
                #pragma unroll
                for (int ct = 0; ct < 4; ++ct)
                    mma_tf32(acc1[rt][ct], a, reinterpret_cast<const uint32_t*>(&bb[cur][ct]));
            }
        }
    }
    __syncthreads();   // all warps done READING sA

    // write hidden (bias + relu, tf32, permuted) over sA
    #pragma unroll
    for (int rt = 0; rt < 4; ++rt) {
        #pragma unroll
        for (int ct = 0; ct < 4; ++ct) {
            int r = rt * 16 + lq;
            int cbase = warp * 32 + ct * 8;
            int c = cbase + lr * 2;
            float b0 = __ldg(bn1 + c), b1 = __ldg(bn1 + c + 1);
            uint32_t* d0 = sA + r * LDH + cbase + p0;
            uint32_t* d1 = sA + (r + 8) * LDH + cbase + p0;
            d0[0] = f2tf(fmaxf(acc1[rt][ct][0] + b0, 0.f));
            d0[2] = f2tf(fmaxf(acc1[rt][ct][1] + b1, 0.f));
            d1[0] = f2tf(fmaxf(acc1[rt][ct][2] + b0, 0.f));
            d1[2] = f2tf(fmaxf(acc1[rt][ct][3] + b1, 0.f));
        }
    }
    __syncthreads();

    // ---- GEMM2: out = nodes + hidden @ Wn2 + bn2
    {
        const int wr = warp >> 2;           // 0..1
        const int wc = warp & 3;            // 0..3
        const int g0 = wc * 4;
        const int KT = H / 8;               // 32
        const int NG = D / 8;               // 16

        float acc[2][4][4];
        #pragma unroll
        for (int i = 0; i < 2; ++i)
            #pragma unroll
            for (int j = 0; j < 4; ++j)
                #pragma unroll
                for (int k = 0; k < 4; ++k) acc[i][j][k] = 0.f;

        uint2 bb[2][4];
        #pragma unroll
        for (int ct = 0; ct < 4; ++ct)
            bb[0][ct] = g_pWn2[(size_t)(g0 + ct) * 32 + lane];

        #pragma unroll 1
        for (int kt = 0; kt < KT; ++kt) {
            const int cur = kt & 1;
            if (kt + 1 < KT) {
                #pragma unroll
                for (int ct = 0; ct < 4; ++ct)
                    bb[cur ^ 1][ct] = g_pWn2[(size_t)((kt + 1) * NG + g0 + ct) * 32 + lane];
            }
            const int kb = kt * 8;
            #pragma unroll
            for (int rt = 0; rt < 2; ++rt) {
                uint32_t a[4];
                load_afrag(a, sA, wr * 32 + rt * 16 + lq, LDH, kb, lr);
                #pragma unroll
                for (int ct = 0; ct < 4; ++ct)
                    mma_tf32(acc[rt][ct], a, reinterpret_cast<const uint32_t*>(&bb[cur][ct]));
            }
        }
        #pragma unroll
        for (int rt = 0; rt < 2; ++rt) {
            #pragma unroll
            for (int ct = 0; ct < 4; ++ct) {
                int r = wr * 32 + rt * 16 + lq;
                int c = wc * 32 + ct * 8 + lr * 2;
                float b0 = __ldg(bn2 + c), b1 = __ldg(bn2 + c + 1);
                int gr = row0 + r;
                if (gr < N_NODES) {
                    float2 xn = *reinterpret_cast<const float2*>(nodes + (size_t)gr * D + c);
                    float2 v  = make_float2(xn.x + acc[rt][ct][0] + b0,
                                            xn.y + acc[rt][ct][1] + b1);
                    *reinterpret_cast<float2*>(out + (size_t)gr * D + c) = v;
                }
                int gr2 = gr + 8;
                if (gr2 < N_NODES) {
                    float2 xn = *reinterpret_cast<const float2*>(nodes + (size_t)gr2 * D + c);
                    float2 v  = make_float2(xn.x + acc[rt][ct][2] + b0,
                                            xn.y + acc[rt][ct][3] + b1);
                    *reinterpret_cast<float2*>(out + (size_t)gr2 * D + c) = v;
                }
            }
        }
    }
}

// ---------------------------------------------------------------------------
// launch
// ---------------------------------------------------------------------------
extern "C" void kernel_launch(void* const* d_in, const int* in_sizes, int n_in,
                              void* d_out, int out_size)
{
    const float* nodes     = (const float*)d_in[0];
    const int*   senders   = (const int*)  d_in[1];
    const int*   receivers = (const int*)  d_in[2];
    const float* Wm1 = (const float*)d_in[3];
    const float* bm1 = (const float*)d_in[4];
    const float* Wm2 = (const float*)d_in[5];
    const float* bm2 = (const float*)d_in[6];
    const float* Wn1 = (const float*)d_in[7];
    const float* bn1 = (const float*)d_in[8];
    const float* Wn2 = (const float*)d_in[9];
    const float* bn2 = (const float*)d_in[10];
    float* out = (float*)d_out;

    const int SMEM1 = (TILE_M * LDX + TILE_M * LDH) * 4;   // 102400 B -> 2 CTA/SM
    const int SMEM3 = (TILE_M * LDH) * 4;                  // 67584 B  -> 2 CTA/SM
    cudaFuncSetAttribute(msg_mlp_kernel,  cudaFuncAttributeMaxDynamicSharedMemorySize, SMEM1);
    cudaFuncSetAttribute(node_mlp_kernel, cudaFuncAttributeMaxDynamicSharedMemorySize, SMEM3);

    // pack all weights in one launch
    {
        int n = 16*32*32 + 32*16*32 + 32*32*32 + 32*16*32;   // 81920
        pack_all_kernel<<<(n + 255) / 256, 256>>>(Wm1, Wm2, Wn1, Wn2);
    }

    // m = MLP1(nodes); also zeroes g_agg per tile
    msg_mlp_kernel<<<NTILES, 256, SMEM1>>>(nodes, bm1, bm2);

    // agg[recv] += m[send]
    {
        long long threads = (long long)N_EDGES * 32;
        int blocks = (int)((threads + 255) / 256);
        scatter_kernel<<<blocks, 256>>>(senders, receivers);
    }

    // out = nodes + MLP2([nodes||agg])
    node_mlp_kernel<<<NTILES, 256, SMEM3>>>(nodes, bn1, bn2, out);
}

// round 13
// speedup vs baseline: 1.6759x; 1.6759x over previous
#include <cuda_runtime.h>
#include <stdint.h>

#define N_NODES 100000
#define N_EDGES 600000
#define D 128
#define H 256
#define TILE_M 64
#define NTILES ((N_NODES + TILE_M - 1) / TILE_M)   // 1563

#define LDX 132   // smem row stride (floats), 128-col tile
#define LDH 260   // smem row stride (floats), 256-col tile

// Scratch (allocation-free rule: device globals)
__device__ float g_m[(size_t)N_NODES * D];
__device__ float g_agg[(size_t)N_NODES * D];

// Pre-packed tf32 weights in mma-fragment order:
//   pW[(kt*Ng + g)*32 + lane] = { tf32(W[kt*8   + lane%4][g*8 + lane/4]),
//                                 tf32(W[kt*8+4 + lane%4][g*8 + lane/4]) }
__device__ uint2 g_pWm1[16 * 32 * 32];
__device__ uint2 g_pWm2[32 * 16 * 32];
__device__ uint2 g_pWn1[32 * 32 * 32];
__device__ uint2 g_pWn2[32 * 16 * 32];

// ---------------------------------------------------------------------------
// helpers
// ---------------------------------------------------------------------------
__device__ __forceinline__ uint32_t f2tf(float f) {
    uint32_t u;
    asm("cvt.rna.tf32.f32 %0, %1;" : "=r"(u) : "f"(f));
    return u;
}

__device__ __forceinline__ void mma_tf32(float c[4], const uint32_t a[4], const uint32_t* b) {
    asm volatile(
        "mma.sync.aligned.m16n8k8.row.col.f32.tf32.tf32.f32 "
        "{%0,%1,%2,%3}, {%4,%5,%6,%7}, {%8,%9}, {%0,%1,%2,%3};\n"
        : "+f"(c[0]), "+f"(c[1]), "+f"(c[2]), "+f"(c[3])
        : "r"(a[0]), "r"(a[1]), "r"(a[2]), "r"(a[3]),
          "r"(b[0]), "r"(b[1]));
}

__device__ __forceinline__ void load_afrag(uint32_t a[4], const uint32_t* s,
                                           int row, int ld, int kb, int lr)
{
    const uint32_t* base = s + row * ld + kb + lr;
    a[0] = base[0];
    a[1] = base[8 * ld];
    a[2] = base[4];
    a[3] = base[8 * ld + 4];
}

// ---------------------------------------------------------------------------
// One fused pack kernel: all four weight matrices -> fragment-ordered tf32
// ---------------------------------------------------------------------------
__device__ __forceinline__ void pack_one(const float* __restrict__ W,
                                         uint2* __restrict__ pW,
                                         int id, int Ng, int N)
{
    int lane = id & 31;
    int g    = (id >> 5) % Ng;
    int kt   = (id >> 5) / Ng;
    int lr = lane & 3, lq = lane >> 2;
    int col = g * 8 + lq;
    uint2 v;
    v.x = f2tf(W[(size_t)(kt * 8 + lr)     * N + col]);
    v.y = f2tf(W[(size_t)(kt * 8 + 4 + lr) * N + col]);
    pW[id] = v;
}

__global__ void pack_all_kernel(const float* __restrict__ Wm1, const float* __restrict__ Wm2,
                                const float* __restrict__ Wn1, const float* __restrict__ Wn2)
{
    const int n1 = 16 * 32 * 32;
    const int n2 = 32 * 16 * 32;
    const int n3 = 32 * 32 * 32;
    const int n4 = 32 * 16 * 32;
    int id = blockIdx.x * 256 + threadIdx.x;
    if (id < n1)                     pack_one(Wm1, g_pWm1, id,                32, H);
    else if (id < n1 + n2)           pack_one(Wm2, g_pWm2, id - n1,           16, D);
    else if (id < n1 + n2 + n3)      pack_one(Wn1, g_pWn1, id - n1 - n2,      32, H);
    else if (id < n1 + n2 + n3 + n4) pack_one(Wn2, g_pWn2, id - n1 - n2 - n3, 16, D);
}

// 4-stage, distance-3 B-fragment pipeline over one GEMM k-loop.
// KT must be divisible by 4. Buffer for k-tile k is bb[k % 4].
#define B_PIPE_PROLOGUE(pW, g0, NG)                                            \
    uint2 bb[4][4];                                                            \
    _Pragma("unroll")                                                          \
    for (int s = 0; s < 3; ++s)                                                \
        _Pragma("unroll")                                                      \
        for (int ct = 0; ct < 4; ++ct)                                         \
            bb[s][ct] = pW[(size_t)(s * NG + g0 + ct) * 32 + lane];

#define B_PIPE_PREFETCH(pW, g0, NG, KT, k, j)                                  \
    if ((k) + 3 < (KT)) {                                                      \
        _Pragma("unroll")                                                      \
        for (int ct = 0; ct < 4; ++ct)                                         \
            bb[((j) + 3) & 3][ct] =                                            \
                pW[(size_t)(((k) + 3) * NG + g0 + ct) * 32 + lane];            \
    }

// ---------------------------------------------------------------------------
// Kernel 1: m = relu(X @ Wm1 + bm1) @ Wm2 + bm2   + zero g_agg rows
//   64-row tiles, 256 threads (8 warps), 2 CTAs/SM.
// ---------------------------------------------------------------------------
__global__ __launch_bounds__(256, 2)
void msg_mlp_kernel(const float* __restrict__ nodes,
                    const float* __restrict__ bm1, const float* __restrict__ bm2)
{
    extern __shared__ uint32_t smem[];
    uint32_t* sX = smem;                    // [64][LDX]
    uint32_t* sH = smem + TILE_M * LDX;     // [64][LDH]

    const int row0 = blockIdx.x * TILE_M;
    const int tid  = threadIdx.x;
    const int warp = tid >> 5;
    const int lane = tid & 31;
    const int lq   = lane >> 2;
    const int lr   = lane & 3;

    // zero this tile's g_agg rows
    for (int i = tid; i < TILE_M * (D / 4); i += 256) {
        int r  = i >> 5;
        int c4 = (i & 31) * 4;
        int gr = row0 + r;
        if (gr < N_NODES)
            *reinterpret_cast<float4*>(g_agg + (size_t)gr * D + c4) =
                make_float4(0.f, 0.f, 0.f, 0.f);
    }

    // stage X tile (fp32 -> tf32)
    for (int i = tid; i < TILE_M * (D / 4); i += 256) {
        int r  = i >> 5;
        int c4 = (i & 31) * 4;
        float4 v = make_float4(0.f, 0.f, 0.f, 0.f);
        int gr = row0 + r;
        if (gr < N_NODES) v = *reinterpret_cast<const float4*>(nodes + (size_t)gr * D + c4);
        uint32_t* dst = sX + r * LDX + c4;
        dst[0] = f2tf(v.x); dst[1] = f2tf(v.y); dst[2] = f2tf(v.z); dst[3] = f2tf(v.w);
    }
    __syncthreads();

    // ---- GEMM1: hidden[64x256] = relu(X @ Wm1 + bm1); warp owns 32 cols
    {
        const int g0 = warp * 4;
        const int KT = D / 8;               // 16
        const int NG = H / 8;               // 32

        float acc[4][4][4];
        #pragma unroll
        for (int i = 0; i < 4; ++i)
            #pragma unroll
            for (int j = 0; j < 4; ++j)
                #pragma unroll
                for (int k = 0; k < 4; ++k) acc[i][j][k] = 0.f;

        B_PIPE_PROLOGUE(g_pWm1, g0, NG)

        #pragma unroll 1
        for (int kt = 0; kt < KT; kt += 4) {
            #pragma unroll
            for (int j = 0; j < 4; ++j) {
                const int k = kt + j;
                B_PIPE_PREFETCH(g_pWm1, g0, NG, KT, k, j)
                const int kb = k * 8;
                #pragma unroll
                for (int rt = 0; rt < 4; ++rt) {
                    uint32_t a[4];
                    load_afrag(a, sX, rt * 16 + lq, LDX, kb, lr);
                    #pragma unroll
                    for (int ct = 0; ct < 4; ++ct)
                        mma_tf32(acc[rt][ct], a, reinterpret_cast<const uint32_t*>(&bb[j][ct]));
                }
            }
        }
        // bias + relu -> sH (tf32)
        #pragma unroll
        for (int rt = 0; rt < 4; ++rt) {
            #pragma unroll
            for (int ct = 0; ct < 4; ++ct) {
                int r = rt * 16 + lq;
                int c = warp * 32 + ct * 8 + lr * 2;
                float b0 = __ldg(bm1 + c), b1 = __ldg(bm1 + c + 1);
                sH[r * LDH + c]           = f2tf(fmaxf(acc[rt][ct][0] + b0, 0.f));
                sH[r * LDH + c + 1]       = f2tf(fmaxf(acc[rt][ct][1] + b1, 0.f));
                sH[(r + 8) * LDH + c]     = f2tf(fmaxf(acc[rt][ct][2] + b0, 0.f));
                sH[(r + 8) * LDH + c + 1] = f2tf(fmaxf(acc[rt][ct][3] + b1, 0.f));
            }
        }
    }
    __syncthreads();

    // ---- GEMM2: m[64x128] = hidden @ Wm2 + bm2
    {
        const int wr = warp >> 2;           // 0..1 -> rows wr*32
        const int wc = warp & 3;            // 0..3 -> cols wc*32
        const int g0 = wc * 4;
        const int KT = H / 8;               // 32
        const int NG = D / 8;               // 16

        float acc[2][4][4];
        #pragma unroll
        for (int i = 0; i < 2; ++i)
            #pragma unroll
            for (int j = 0; j < 4; ++j)
                #pragma unroll
                for (int k = 0; k < 4; ++k) acc[i][j][k] = 0.f;

        B_PIPE_PROLOGUE(g_pWm2, g0, NG)

        #pragma unroll 1
        for (int kt = 0; kt < KT; kt += 4) {
            #pragma unroll
            for (int j = 0; j < 4; ++j) {
                const int k = kt + j;
                B_PIPE_PREFETCH(g_pWm2, g0, NG, KT, k, j)
                const int kb = k * 8;
                #pragma unroll
                for (int rt = 0; rt < 2; ++rt) {
                    uint32_t a[4];
                    load_afrag(a, sH, wr * 32 + rt * 16 + lq, LDH, kb, lr);
                    #pragma unroll
                    for (int ct = 0; ct < 4; ++ct)
                        mma_tf32(acc[rt][ct], a, reinterpret_cast<const uint32_t*>(&bb[j][ct]));
                }
            }
        }
        #pragma unroll
        for (int rt = 0; rt < 2; ++rt) {
            #pragma unroll
            for (int ct = 0; ct < 4; ++ct) {
                int r = wr * 32 + rt * 16 + lq;
                int c = wc * 32 + ct * 8 + lr * 2;
                float b0 = __ldg(bm2 + c), b1 = __ldg(bm2 + c + 1);
                int gr = row0 + r;
                if (gr < N_NODES) {
                    float2 v = make_float2(acc[rt][ct][0] + b0, acc[rt][ct][1] + b1);
                    *reinterpret_cast<float2*>(g_m + (size_t)gr * D + c) = v;
                }
                int gr2 = gr + 8;
                if (gr2 < N_NODES) {
                    float2 v = make_float2(acc[rt][ct][2] + b0, acc[rt][ct][3] + b1);
                    *reinterpret_cast<float2*>(g_m + (size_t)gr2 * D + c) = v;
                }
            }
        }
    }
}

// ---------------------------------------------------------------------------
// Kernel 2: agg[recv] += m[send]   (one warp per edge, vector red to L2)
// ---------------------------------------------------------------------------
__global__ __launch_bounds__(256)
void scatter_kernel(const int* __restrict__ senders, const int* __restrict__ receivers)
{
    int e = (blockIdx.x * 256 + threadIdx.x) >> 5;
    int lane = threadIdx.x & 31;
    if (e >= N_EDGES) return;
    int s = __ldg(senders + e);
    int r = __ldg(receivers + e);
    float4 v = *reinterpret_cast<const float4*>(g_m + (size_t)s * D + lane * 4);
    float* dst = g_agg + (size_t)r * D + lane * 4;
    asm volatile("red.global.add.v4.f32 [%0], {%1,%2,%3,%4};"
                 :: "l"(dst), "f"(v.x), "f"(v.y), "f"(v.z), "f"(v.w)
                 : "memory");
}

// ---------------------------------------------------------------------------
// Kernel 3: out = nodes + relu([nodes||agg] @ Wn1 + bn1) @ Wn2 + bn2
//   64-row tiles, 256 threads, 2 CTAs/SM.
// ---------------------------------------------------------------------------
__global__ __launch_bounds__(256, 2)
void node_mlp_kernel(const float* __restrict__ nodes,
                     const float* __restrict__ bn1, const float* __restrict__ bn2,
                     float* __restrict__ out)
{
    extern __shared__ uint32_t smem[];
    uint32_t* sA = smem;   // [64][LDH]; A = [X||agg], later reused as hidden

    const int row0 = blockIdx.x * TILE_M;
    const int tid  = threadIdx.x;
    const int warp = tid >> 5;
    const int lane = tid & 31;
    const int lq   = lane >> 2;
    const int lr   = lane & 3;

    // stage A = [nodes || agg], 64 x 256, tf32
    for (int i = tid; i < TILE_M * (2 * D / 4); i += 256) {
        int r  = i >> 6;
        int c4 = (i & 63) * 4;
        float4 v = make_float4(0.f, 0.f, 0.f, 0.f);
        int gr = row0 + r;
        if (gr < N_NODES) {
            if (c4 < D) v = *reinterpret_cast<const float4*>(nodes + (size_t)gr * D + c4);
            else        v = *reinterpret_cast<const float4*>(g_agg + (size_t)gr * D + (c4 - D));
        }
        uint32_t* dst = sA + r * LDH + c4;
        dst[0] = f2tf(v.x); dst[1] = f2tf(v.y); dst[2] = f2tf(v.z); dst[3] = f2tf(v.w);
    }
    __syncthreads();

    // ---- GEMM1: hidden[64x256] = relu(A @ Wn1 + bn1); warp owns 32 cols
    float acc1[4][4][4];
    #pragma unroll
    for (int i = 0; i < 4; ++i)
        #pragma unroll
        for (int j = 0; j < 4; ++j)
            #pragma unroll
            for (int k = 0; k < 4; ++k) acc1[i][j][k] = 0.f;

    {
        const int g0 = warp * 4;
        const int KT = (2 * D) / 8;         // 32
        const int NG = H / 8;               // 32

        B_PIPE_PROLOGUE(g_pWn1, g0, NG)

        #pragma unroll 1
        for (int kt = 0; kt < KT; kt += 4) {
            #pragma unroll
            for (int j = 0; j < 4; ++j) {
                const int k = kt + j;
                B_PIPE_PREFETCH(g_pWn1, g0, NG, KT, k, j)
                const int kb = k * 8;
                #pragma unroll
                for (int rt = 0; rt < 4; ++rt) {
                    uint32_t a[4];
                    load_afrag(a, sA, rt * 16 + lq, LDH, kb, lr);
                    #pragma unroll
                    for (int ct = 0; ct < 4; ++ct)
                        mma_tf32(acc1[rt][ct], a, reinterpret_cast<const uint32_t*>(&bb[j][ct]));
                }
            }
        }
    }
    __syncthreads();   // all warps done READING sA

    // write hidden (bias + relu, tf32) over sA
    #pragma unroll
    for (int rt = 0; rt < 4; ++rt) {
        #pragma unroll
        for (int ct = 0; ct < 4; ++ct) {
            int r = rt * 16 + lq;
            int c = warp * 32 + ct * 8 + lr * 2;
            float b0 = __ldg(bn1 + c), b1 = __ldg(bn1 + c + 1);
            sA[r * LDH + c]           = f2tf(fmaxf(acc1[rt][ct][0] + b0, 0.f));
            sA[r * LDH + c + 1]       = f2tf(fmaxf(acc1[rt][ct][1] + b1, 0.f));
            sA[(r + 8) * LDH + c]     = f2tf(fmaxf(acc1[rt][ct][2] + b0, 0.f));
            sA[(r + 8) * LDH + c + 1] = f2tf(fmaxf(acc1[rt][ct][3] + b1, 0.f));
        }
    }
    __syncthreads();

    // ---- GEMM2: out = nodes + hidden @ Wn2 + bn2
    {
        const int wr = warp >> 2;           // 0..1
        const int wc = warp & 3;            // 0..3
        const int g0 = wc * 4;
        const int KT = H / 8;               // 32
        const int NG = D / 8;               // 16

        float acc[2][4][4];
        #pragma unroll
        for (int i = 0; i < 2; ++i)
            #pragma unroll
            for (int j = 0; j < 4; ++j)
                #pragma unroll
                for (int k = 0; k < 4; ++k) acc[i][j][k] = 0.f;

        B_PIPE_PROLOGUE(g_pWn2, g0, NG)

        #pragma unroll 1
        for (int kt = 0; kt < KT; kt += 4) {
            #pragma unroll
            for (int j = 0; j < 4; ++j) {
                const int k = kt + j;
                B_PIPE_PREFETCH(g_pWn2, g0, NG, KT, k, j)
                const int kb = k * 8;
                #pragma unroll
                for (int rt = 0; rt < 2; ++rt) {
                    uint32_t a[4];
                    load_afrag(a, sA, wr * 32 + rt * 16 + lq, LDH, kb, lr);
                    #pragma unroll
                    for (int ct = 0; ct < 4; ++ct)
                        mma_tf32(acc[rt][ct], a, reinterpret_cast<const uint32_t*>(&bb[j][ct]));
                }
            }
        }
        #pragma unroll
        for (int rt = 0; rt < 2; ++rt) {
            #pragma unroll
            for (int ct = 0; ct < 4; ++ct) {
                int r = wr * 32 + rt * 16 + lq;
                int c = wc * 32 + ct * 8 + lr * 2;
                float b0 = __ldg(bn2 + c), b1 = __ldg(bn2 + c + 1);
                int gr = row0 + r;
                if (gr < N_NODES) {
                    float2 xn = *reinterpret_cast<const float2*>(nodes + (size_t)gr * D + c);
                    float2 v  = make_float2(xn.x + acc[rt][ct][0] + b0,
                                            xn.y + acc[rt][ct][1] + b1);
                    *reinterpret_cast<float2*>(out + (size_t)gr * D + c) = v;
                }
                int gr2 = gr + 8;
                if (gr2 < N_NODES) {
                    float2 xn = *reinterpret_cast<const float2*>(nodes + (size_t)gr2 * D + c);
                    float2 v  = make_float2(xn.x + acc[rt][ct][2] + b0,
                                            xn.y + acc[rt][ct][3] + b1);
                    *reinterpret_cast<float2*>(out + (size_t)gr2 * D + c) = v;
                }
            }
        }
    }
}

// ---------------------------------------------------------------------------
// launch
// ---------------------------------------------------------------------------
extern "C" void kernel_launch(void* const* d_in, const int* in_sizes, int n_in,
                              void* d_out, int out_size)
{
    const float* nodes     = (const float*)d_in[0];
    const int*   senders   = (const int*)  d_in[1];
    const int*   receivers = (const int*)  d_in[2];
    const float* Wm1 = (const float*)d_in[3];
    const float* bm1 = (const float*)d_in[4];
    const float* Wm2 = (const float*)d_in[5];
    const float* bm2 = (const float*)d_in[6];
    const float* Wn1 = (const float*)d_in[7];
    const float* bn1 = (const float*)d_in[8];
    const float* Wn2 = (const float*)d_in[9];
    const float* bn2 = (const float*)d_in[10];
    float* out = (float*)d_out;

    const int SMEM1 = (TILE_M * LDX + TILE_M * LDH) * 4;   // 100352 B -> 2 CTA/SM
    const int SMEM3 = (TILE_M * LDH) * 4;                  // 66560 B  -> 2 CTA/SM
    cudaFuncSetAttribute(msg_mlp_kernel,  cudaFuncAttributeMaxDynamicSharedMemorySize, SMEM1);
    cudaFuncSetAttribute(node_mlp_kernel, cudaFuncAttributeMaxDynamicSharedMemorySize, SMEM3);

    // pack all weights in one launch
    {
        int n = 16*32*32 + 32*16*32 + 32*32*32 + 32*16*32;   // 81920
        pack_all_kernel<<<(n + 255) / 256, 256>>>(Wm1, Wm2, Wn1, Wn2);
    }

    // m = MLP1(nodes); also zeroes g_agg per tile
    msg_mlp_kernel<<<NTILES, 256, SMEM1>>>(nodes, bm1, bm2);

    // agg[recv] += m[send]
    {
        long long threads = (long long)N_EDGES * 32;
        int blocks = (int)((threads + 255) / 256);
        scatter_kernel<<<blocks, 256>>>(senders, receivers);
    }

    // out = nodes + MLP2([nodes||agg])
    node_mlp_kernel<<<NTILES, 256, SMEM3>>>(nodes, bn1, bn2, out);
}

// round 15
// speedup vs baseline: 2.1305x; 1.2712x over previous
#include <cuda_runtime.h>
#include <cuda_fp16.h>
#include <stdint.h>

#define N_NODES 100000
#define N_EDGES 600000
#define D 128
#define H 256
#define TILE_M 64
#define NTILES ((N_NODES + TILE_M - 1) / TILE_M)   // 1563

#define LDXh 136   // smem row stride (halves), 128-col tile
#define LDHh 264   // smem row stride (halves), 256-col tile

// Scratch (allocation-free rule: device globals)
__device__ __half g_m[(size_t)N_NODES * D];
__device__ float  g_agg[(size_t)N_NODES * D];

// Pre-packed fp16 weights in m16n8k16-fragment order:
//   pW[(kt*Ng + g)*32 + lane] = { half2(W[kt*16+2lr][col],   W[kt*16+2lr+1][col]),
//                                 half2(W[kt*16+8+2lr][col], W[kt*16+8+2lr+1][col]) }
//   with col = g*8 + lane/4, lr = lane%4
__device__ uint2 g_pWm1[ 8 * 32 * 32];   // Wm1: K=128 -> KT=8,  N=256 -> NG=32
__device__ uint2 g_pWm2[16 * 16 * 32];   // Wm2: K=256 -> KT=16, N=128 -> NG=16
__device__ uint2 g_pWn1[16 * 32 * 32];   // Wn1: K=256 -> KT=16, N=256 -> NG=32
__device__ uint2 g_pWn2[16 * 16 * 32];   // Wn2: K=256 -> KT=16, N=128 -> NG=16

// ---------------------------------------------------------------------------
// helpers
// ---------------------------------------------------------------------------
__device__ __forceinline__ uint32_t f2h2(float lo, float hi) {
    __half2 h = __floats2half2_rn(lo, hi);
    return *reinterpret_cast<uint32_t*>(&h);
}

__device__ __forceinline__ void mma_f16(float c[4], const uint32_t a[4], const uint32_t* b) {
    asm volatile(
        "mma.sync.aligned.m16n8k16.row.col.f32.f16.f16.f32 "
        "{%0,%1,%2,%3}, {%4,%5,%6,%7}, {%8,%9}, {%0,%1,%2,%3};\n"
        : "+f"(c[0]), "+f"(c[1]), "+f"(c[2]), "+f"(c[3])
        : "r"(a[0]), "r"(a[1]), "r"(a[2]), "r"(a[3]),
          "r"(b[0]), "r"(b[1]));
}

// A fragment for m16n8k16 (rows lq/lq+8, k = kb+2lr..+1 and kb+8+2lr..+1)
__device__ __forceinline__ void load_afrag(uint32_t a[4], const __half* s,
                                           int row, int ld, int kb, int lr)
{
    const __half* base = s + row * ld + kb + lr * 2;
    a[0] = *reinterpret_cast<const uint32_t*>(base);
    a[1] = *reinterpret_cast<const uint32_t*>(base + 8 * ld);
    a[2] = *reinterpret_cast<const uint32_t*>(base + 8);
    a[3] = *reinterpret_cast<const uint32_t*>(base + 8 * ld + 8);
}

// ---------------------------------------------------------------------------
// One fused pack kernel: all four weight matrices -> fragment-ordered fp16
// ---------------------------------------------------------------------------
__device__ __forceinline__ void pack_one(const float* __restrict__ W,
                                         uint2* __restrict__ pW,
                                         int id, int Ng, int N)
{
    int lane = id & 31;
    int g    = (id >> 5) % Ng;
    int kt   = (id >> 5) / Ng;
    int lr = lane & 3, lq = lane >> 2;
    int col = g * 8 + lq;
    int k0 = kt * 16 + lr * 2;
    uint2 v;
    v.x = f2h2(W[(size_t)k0       * N + col], W[(size_t)(k0 + 1) * N + col]);
    v.y = f2h2(W[(size_t)(k0 + 8) * N + col], W[(size_t)(k0 + 9) * N + col]);
    pW[id] = v;
}

__global__ void pack_all_kernel(const float* __restrict__ Wm1, const float* __restrict__ Wm2,
                                const float* __restrict__ Wn1, const float* __restrict__ Wn2)
{
    const int n1 =  8 * 32 * 32;
    const int n2 = 16 * 16 * 32;
    const int n3 = 16 * 32 * 32;
    const int n4 = 16 * 16 * 32;
    int id = blockIdx.x * 256 + threadIdx.x;
    if (id < n1)                     pack_one(Wm1, g_pWm1, id,                32, H);
    else if (id < n1 + n2)           pack_one(Wm2, g_pWm2, id - n1,           16, D);
    else if (id < n1 + n2 + n3)      pack_one(Wn1, g_pWn1, id - n1 - n2,      32, H);
    else if (id < n1 + n2 + n3 + n4) pack_one(Wn2, g_pWn2, id - n1 - n2 - n3, 16, D);
}

// 4-stage, distance-3 B-fragment pipeline (KT % 4 == 0)
#define B_PIPE_PROLOGUE(pW, g0, NG)                                            \
    uint2 bb[4][4];                                                            \
    _Pragma("unroll")                                                          \
    for (int s = 0; s < 3; ++s)                                                \
        _Pragma("unroll")                                                      \
        for (int ct = 0; ct < 4; ++ct)                                         \
            bb[s][ct] = pW[(size_t)(s * NG + g0 + ct) * 32 + lane];

#define B_PIPE_PREFETCH(pW, g0, NG, KT, k, j)                                  \
    if ((k) + 3 < (KT)) {                                                      \
        _Pragma("unroll")                                                      \
        for (int ct = 0; ct < 4; ++ct)                                         \
            bb[((j) + 3) & 3][ct] =                                            \
                pW[(size_t)(((k) + 3) * NG + g0 + ct) * 32 + lane];            \
    }

// ---------------------------------------------------------------------------
// Kernel 1: m = relu(X @ Wm1 + bm1) @ Wm2 + bm2   + zero g_agg rows
//   64-row tiles, 256 threads (8 warps), 2 CTAs/SM.
// ---------------------------------------------------------------------------
__global__ __launch_bounds__(256, 2)
void msg_mlp_kernel(const float* __restrict__ nodes,
                    const float* __restrict__ bm1, const float* __restrict__ bm2)
{
    extern __shared__ __half smemh[];
    __half* sX = smemh;                     // [64][LDXh] fp16
    __half* sH = smemh + TILE_M * LDXh;     // [64][LDHh] fp16

    const int row0 = blockIdx.x * TILE_M;
    const int tid  = threadIdx.x;
    const int warp = tid >> 5;
    const int lane = tid & 31;
    const int lq   = lane >> 2;
    const int lr   = lane & 3;

    // zero this tile's g_agg rows
    for (int i = tid; i < TILE_M * (D / 4); i += 256) {
        int r  = i >> 5;
        int c4 = (i & 31) * 4;
        int gr = row0 + r;
        if (gr < N_NODES)
            *reinterpret_cast<float4*>(g_agg + (size_t)gr * D + c4) =
                make_float4(0.f, 0.f, 0.f, 0.f);
    }

    // stage X tile (fp32 -> fp16)
    for (int i = tid; i < TILE_M * (D / 4); i += 256) {
        int r  = i >> 5;
        int c4 = (i & 31) * 4;
        float4 v = make_float4(0.f, 0.f, 0.f, 0.f);
        int gr = row0 + r;
        if (gr < N_NODES) v = *reinterpret_cast<const float4*>(nodes + (size_t)gr * D + c4);
        *reinterpret_cast<uint2*>(sX + r * LDXh + c4) =
            make_uint2(f2h2(v.x, v.y), f2h2(v.z, v.w));
    }
    __syncthreads();

    // ---- GEMM1: hidden[64x256] = relu(X @ Wm1 + bm1); warp owns 32 cols
    {
        const int g0 = warp * 4;
        const int KT = D / 16;              // 8
        const int NG = H / 8;               // 32

        float acc[4][4][4];
        #pragma unroll
        for (int i = 0; i < 4; ++i)
            #pragma unroll
            for (int j = 0; j < 4; ++j)
                #pragma unroll
                for (int k = 0; k < 4; ++k) acc[i][j][k] = 0.f;

        B_PIPE_PROLOGUE(g_pWm1, g0, NG)

        #pragma unroll 1
        for (int kt = 0; kt < KT; kt += 4) {
            #pragma unroll
            for (int j = 0; j < 4; ++j) {
                const int k = kt + j;
                B_PIPE_PREFETCH(g_pWm1, g0, NG, KT, k, j)
                const int kb = k * 16;
                #pragma unroll
                for (int rt = 0; rt < 4; ++rt) {
                    uint32_t a[4];
                    load_afrag(a, sX, rt * 16 + lq, LDXh, kb, lr);
                    #pragma unroll
                    for (int ct = 0; ct < 4; ++ct)
                        mma_f16(acc[rt][ct], a, reinterpret_cast<const uint32_t*>(&bb[j][ct]));
                }
            }
        }
        // bias + relu -> sH (fp16)
        #pragma unroll
        for (int rt = 0; rt < 4; ++rt) {
            #pragma unroll
            for (int ct = 0; ct < 4; ++ct) {
                int r = rt * 16 + lq;
                int c = warp * 32 + ct * 8 + lr * 2;
                float b0 = __ldg(bm1 + c), b1 = __ldg(bm1 + c + 1);
                *reinterpret_cast<uint32_t*>(sH + r * LDHh + c) =
                    f2h2(fmaxf(acc[rt][ct][0] + b0, 0.f), fmaxf(acc[rt][ct][1] + b1, 0.f));
                *reinterpret_cast<uint32_t*>(sH + (r + 8) * LDHh + c) =
                    f2h2(fmaxf(acc[rt][ct][2] + b0, 0.f), fmaxf(acc[rt][ct][3] + b1, 0.f));
            }
        }
    }
    __syncthreads();

    // ---- GEMM2: m[64x128] = hidden @ Wm2 + bm2  (stored fp16)
    {
        const int wr = warp >> 2;           // 0..1 -> rows wr*32
        const int wc = warp & 3;            // 0..3 -> cols wc*32
        const int g0 = wc * 4;
        const int KT = H / 16;              // 16
        const int NG = D / 8;               // 16

        float acc[2][4][4];
        #pragma unroll
        for (int i = 0; i < 2; ++i)
            #pragma unroll
            for (int j = 0; j < 4; ++j)
                #pragma unroll
                for (int k = 0; k < 4; ++k) acc[i][j][k] = 0.f;

        B_PIPE_PROLOGUE(g_pWm2, g0, NG)

        #pragma unroll 1
        for (int kt = 0; kt < KT; kt += 4) {
            #pragma unroll
            for (int j = 0; j < 4; ++j) {
                const int k = kt + j;
                B_PIPE_PREFETCH(g_pWm2, g0, NG, KT, k, j)
                const int kb = k * 16;
                #pragma unroll
                for (int rt = 0; rt < 2; ++rt) {
                    uint32_t a[4];
                    load_afrag(a, sH, wr * 32 + rt * 16 + lq, LDHh, kb, lr);
                    #pragma unroll
                    for (int ct = 0; ct < 4; ++ct)
                        mma_f16(acc[rt][ct], a, reinterpret_cast<const uint32_t*>(&bb[j][ct]));
                }
            }
        }
        #pragma unroll
        for (int rt = 0; rt < 2; ++rt) {
            #pragma unroll
            for (int ct = 0; ct < 4; ++ct) {
                int r = wr * 32 + rt * 16 + lq;
                int c = wc * 32 + ct * 8 + lr * 2;
                float b0 = __ldg(bm2 + c), b1 = __ldg(bm2 + c + 1);
                int gr = row0 + r;
                if (gr < N_NODES)
                    *reinterpret_cast<uint32_t*>(g_m + (size_t)gr * D + c) =
                        f2h2(acc[rt][ct][0] + b0, acc[rt][ct][1] + b1);
                int gr2 = gr + 8;
                if (gr2 < N_NODES)
                    *reinterpret_cast<uint32_t*>(g_m + (size_t)gr2 * D + c) =
                        f2h2(acc[rt][ct][2] + b0, acc[rt][ct][3] + b1);
            }
        }
    }
}

// ---------------------------------------------------------------------------
// Kernel 2: agg[recv] += m[send]   (one warp per edge; fp16 read, f32 RED)
// ---------------------------------------------------------------------------
__global__ __launch_bounds__(256)
void scatter_kernel(const int* __restrict__ senders, const int* __restrict__ receivers)
{
    int e = (blockIdx.x * 256 + threadIdx.x) >> 5;
    int lane = threadIdx.x & 31;
    if (e >= N_EDGES) return;
    int s = __ldg(senders + e);
    int r = __ldg(receivers + e);
    uint2 mm = *reinterpret_cast<const uint2*>(g_m + (size_t)s * D + lane * 4);
    __half2 h01 = *reinterpret_cast<__half2*>(&mm.x);
    __half2 h23 = *reinterpret_cast<__half2*>(&mm.y);
    float2 f01 = __half22float2(h01);
    float2 f23 = __half22float2(h23);
    float* dst = g_agg + (size_t)r * D + lane * 4;
    asm volatile("red.global.add.v4.f32 [%0], {%1,%2,%3,%4};"
                 :: "l"(dst), "f"(f01.x), "f"(f01.y), "f"(f23.x), "f"(f23.y)
                 : "memory");
}

// ---------------------------------------------------------------------------
// Kernel 3: out = nodes + relu([nodes||agg] @ Wn1 + bn1) @ Wn2 + bn2
//   64-row tiles, 256 threads, 2 CTAs/SM.
// ---------------------------------------------------------------------------
__global__ __launch_bounds__(256, 2)
void node_mlp_kernel(const float* __restrict__ nodes,
                     const float* __restrict__ bn1, const float* __restrict__ bn2,
                     float* __restrict__ out)
{
    extern __shared__ __half smemh[];
    __half* sA = smemh;   // [64][LDHh]; A = [X||agg], later reused as hidden

    const int row0 = blockIdx.x * TILE_M;
    const int tid  = threadIdx.x;
    const int warp = tid >> 5;
    const int lane = tid & 31;
    const int lq   = lane >> 2;
    const int lr   = lane & 3;

    // stage A = [nodes || agg], 64 x 256, fp16
    for (int i = tid; i < TILE_M * (2 * D / 4); i += 256) {
        int r  = i >> 6;
        int c4 = (i & 63) * 4;
        float4 v = make_float4(0.f, 0.f, 0.f, 0.f);
        int gr = row0 + r;
        if (gr < N_NODES) {
            if (c4 < D) v = *reinterpret_cast<const float4*>(nodes + (size_t)gr * D + c4);
            else        v = *reinterpret_cast<const float4*>(g_agg + (size_t)gr * D + (c4 - D));
        }
        *reinterpret_cast<uint2*>(sA + r * LDHh + c4) =
            make_uint2(f2h2(v.x, v.y), f2h2(v.z, v.w));
    }
    __syncthreads();

    // ---- GEMM1: hidden[64x256] = relu(A @ Wn1 + bn1); warp owns 32 cols
    float acc1[4][4][4];
    #pragma unroll
    for (int i = 0; i < 4; ++i)
        #pragma unroll
        for (int j = 0; j < 4; ++j)
            #pragma unroll
            for (int k = 0; k < 4; ++k) acc1[i][j][k] = 0.f;

    {
        const int g0 = warp * 4;
        const int KT = (2 * D) / 16;        // 16
        const int NG = H / 8;               // 32

        B_PIPE_PROLOGUE(g_pWn1, g0, NG)

        #pragma unroll 1
        for (int kt = 0; kt < KT; kt += 4) {
            #pragma unroll
            for (int j = 0; j < 4; ++j) {
                const int k = kt + j;
                B_PIPE_PREFETCH(g_pWn1, g0, NG, KT, k, j)
                const int kb = k * 16;
                #pragma unroll
                for (int rt = 0; rt < 4; ++rt) {
                    uint32_t a[4];
                    load_afrag(a, sA, rt * 16 + lq, LDHh, kb, lr);
                    #pragma unroll
                    for (int ct = 0; ct < 4; ++ct)
                        mma_f16(acc1[rt][ct], a, reinterpret_cast<const uint32_t*>(&bb[j][ct]));
                }
            }
        }
    }
    __syncthreads();   // all warps done READING sA

    // write hidden (bias + relu, fp16) over sA
    #pragma unroll
    for (int rt = 0; rt < 4; ++rt) {
        #pragma unroll
        for (int ct = 0; ct < 4; ++ct) {
            int r = rt * 16 + lq;
            int c = warp * 32 + ct * 8 + lr * 2;
            float b0 = __ldg(bn1 + c), b1 = __ldg(bn1 + c + 1);
            *reinterpret_cast<uint32_t*>(sA + r * LDHh + c) =
                f2h2(fmaxf(acc1[rt][ct][0] + b0, 0.f), fmaxf(acc1[rt][ct][1] + b1, 0.f));
            *reinterpret_cast<uint32_t*>(sA + (r + 8) * LDHh + c) =
                f2h2(fmaxf(acc1[rt][ct][2] + b0, 0.f), fmaxf(acc1[rt][ct][3] + b1, 0.f));
        }
    }
    __syncthreads();

    // ---- GEMM2: out = nodes + hidden @ Wn2 + bn2
    {
        const int wr = warp >> 2;           // 0..1
        const int wc = warp & 3;            // 0..3
        const int g0 = wc * 4;
        const int KT = H / 16;              // 16
        const int NG = D / 8;               // 16

        float acc[2][4][4];
        #pragma unroll
        for (int i = 0; i < 2; ++i)
            #pragma unroll
            for (int j = 0; j < 4; ++j)
                #pragma unroll
                for (int k = 0; k < 4; ++k) acc[i][j][k] = 0.f;

        B_PIPE_PROLOGUE(g_pWn2, g0, NG)

        #pragma unroll 1
        for (int kt = 0; kt < KT; kt += 4) {
            #pragma unroll
            for (int j = 0; j < 4; ++j) {
                const int k = kt + j;
                B_PIPE_PREFETCH(g_pWn2, g0, NG, KT, k, j)
                const int kb = k * 16;
                #pragma unroll
                for (int rt = 0; rt < 2; ++rt) {
                    uint32_t a[4];
                    load_afrag(a, sA, wr * 32 + rt * 16 + lq, LDHh, kb, lr);
                    #pragma unroll
                    for (int ct = 0; ct < 4; ++ct)
                        mma_f16(acc[rt][ct], a, reinterpret_cast<const uint32_t*>(&bb[j][ct]));
                }
            }
        }
        #pragma unroll
        for (int rt = 0; rt < 2; ++rt) {
            #pragma unroll
            for (int ct = 0; ct < 4; ++ct) {
                int r = wr * 32 + rt * 16 + lq;
                int c = wc * 32 + ct * 8 + lr * 2;
                float b0 = __ldg(bn2 + c), b1 = __ldg(bn2 + c + 1);
                int gr = row0 + r;
                if (gr < N_NODES) {
                    float2 xn = *reinterpret_cast<const float2*>(nodes + (size_t)gr * D + c);
                    float2 v  = make_float2(xn.x + acc[rt][ct][0] + b0,
                                            xn.y + acc[rt][ct][1] + b1);
                    *reinterpret_cast<float2*>(out + (size_t)gr * D + c) = v;
                }
                int gr2 = gr + 8;
                if (gr2 < N_NODES) {
                    float2 xn = *reinterpret_cast<const float2*>(nodes + (size_t)gr2 * D + c);
                    float2 v  = make_float2(xn.x + acc[rt][ct][2] + b0,
                                            xn.y + acc[rt][ct][3] + b1);
                    *reinterpret_cast<float2*>(out + (size_t)gr2 * D + c) = v;
                }
            }
        }
    }
}

// ---------------------------------------------------------------------------
// launch
// ---------------------------------------------------------------------------
extern "C" void kernel_launch(void* const* d_in, const int* in_sizes, int n_in,
                              void* d_out, int out_size)
{
    const float* nodes     = (const float*)d_in[0];
    const int*   senders   = (const int*)  d_in[1];
    const int*   receivers = (const int*)  d_in[2];
    const float* Wm1 = (const float*)d_in[3];
    const float* bm1 = (const float*)d_in[4];
    const float* Wm2 = (const float*)d_in[5];
    const float* bm2 = (const float*)d_in[6];
    const float* Wn1 = (const float*)d_in[7];
    const float* bn1 = (const float*)d_in[8];
    const float* Wn2 = (const float*)d_in[9];
    const float* bn2 = (const float*)d_in[10];
    float* out = (float*)d_out;

    const int SMEM1 = (TILE_M * LDXh + TILE_M * LDHh) * 2;   // 51200 B -> 2 CTA/SM
    const int SMEM3 = (TILE_M * LDHh) * 2;                   // 33792 B -> 2 CTA/SM
    cudaFuncSetAttribute(msg_mlp_kernel,  cudaFuncAttributeMaxDynamicSharedMemorySize, SMEM1);
    cudaFuncSetAttribute(node_mlp_kernel, cudaFuncAttributeMaxDynamicSharedMemorySize, SMEM3);

    // pack all weights in one launch
    {
        int n = 8*32*32 + 16*16*32 + 16*32*32 + 16*16*32;   // 40960
        pack_all_kernel<<<(n + 255) / 256, 256>>>(Wm1, Wm2, Wn1, Wn2);
    }

    // m = MLP1(nodes); also zeroes g_agg per tile
    msg_mlp_kernel<<<NTILES, 256, SMEM1>>>(nodes, bm1, bm2);

    // agg[recv] += m[send]
    {
        long long threads = (long long)N_EDGES * 32;
        int blocks = (int)((threads + 255) / 256);
        scatter_kernel<<<blocks, 256>>>(senders, receivers);
    }

    // out = nodes + MLP2([nodes||agg])
    node_mlp_kernel<<<NTILES, 256, SMEM3>>>(nodes, bn1, bn2, out);
}

// round 16
// speedup vs baseline: 2.1476x; 1.0080x over previous
#include <cuda_runtime.h>
#include <cuda_fp16.h>
#include <stdint.h>

#define N_NODES 100000
#define N_EDGES 600000
#define D 128
#define H 256
#define TILE_M 64
#define NTILES ((N_NODES + TILE_M - 1) / TILE_M)   // 1563

#define LDXh 136   // smem row stride (halves), 128-col tile; 272B rows -> 4r bank walk
#define LDHh 264   // smem row stride (halves), 256-col tile; 528B rows -> 4r bank walk

// Scratch (allocation-free rule: device globals)
__device__ __half g_m[(size_t)N_NODES * D];
__device__ float  g_agg[(size_t)N_NODES * D];

// Pre-packed fp16 weights in m16n8k16-fragment order (see pack_one)
__device__ uint2 g_pWm1[ 8 * 32 * 32];   // Wm1: KT=8,  NG=32
__device__ uint2 g_pWm2[16 * 16 * 32];   // Wm2: KT=16, NG=16
__device__ uint2 g_pWn1[16 * 32 * 32];   // Wn1: KT=16, NG=32
__device__ uint2 g_pWn2[16 * 16 * 32];   // Wn2: KT=16, NG=16

// ---------------------------------------------------------------------------
// helpers
// ---------------------------------------------------------------------------
__device__ __forceinline__ uint32_t f2h2(float lo, float hi) {
    __half2 h = __floats2half2_rn(lo, hi);
    return *reinterpret_cast<uint32_t*>(&h);
}

__device__ __forceinline__ void mma_f16(float c[4], const uint32_t a[4], const uint32_t* b) {
    asm volatile(
        "mma.sync.aligned.m16n8k16.row.col.f32.f16.f16.f32 "
        "{%0,%1,%2,%3}, {%4,%5,%6,%7}, {%8,%9}, {%0,%1,%2,%3};\n"
        : "+f"(c[0]), "+f"(c[1]), "+f"(c[2]), "+f"(c[3])
        : "r"(a[0]), "r"(a[1]), "r"(a[2]), "r"(a[3]),
          "r"(b[0]), "r"(b[1]));
}

// One ldmatrix.x4 loads the full m16n8k16 A fragment (4x 8x8 b16 tiles).
__device__ __forceinline__ void ldsm_x4(uint32_t a[4], uint32_t addr) {
    asm volatile(
        "ldmatrix.sync.aligned.m8n8.x4.shared.b16 {%0,%1,%2,%3}, [%4];"
        : "=r"(a[0]), "=r"(a[1]), "=r"(a[2]), "=r"(a[3]) : "r"(addr));
}

// Per-lane base for ldmatrix over a row-major [rows][ld] half tile:
//   lanes 0-7: rows 0-7 @ col 0 | 8-15: rows 8-15 @ col 0
//   lanes 16-23: rows 0-7 @ col 8 | 24-31: rows 8-15 @ col 8
__device__ __forceinline__ uint32_t ldsm_base(const __half* s, int ld, int lane) {
    uint32_t u = (uint32_t)__cvta_generic_to_shared(s);
    return u + ((uint32_t)((lane & 15) * ld + ((lane >> 4) << 3)) << 1);
}

// ---------------------------------------------------------------------------
// One fused pack kernel: all four weight matrices -> fragment-ordered fp16
// ---------------------------------------------------------------------------
__device__ __forceinline__ void pack_one(const float* __restrict__ W,
                                         uint2* __restrict__ pW,
                                         int id, int Ng, int N)
{
    int lane = id & 31;
    int g    = (id >> 5) % Ng;
    int kt   = (id >> 5) / Ng;
    int lr = lane & 3, lq = lane >> 2;
    int col = g * 8 + lq;
    int k0 = kt * 16 + lr * 2;
    uint2 v;
    v.x = f2h2(W[(size_t)k0       * N + col], W[(size_t)(k0 + 1) * N + col]);
    v.y = f2h2(W[(size_t)(k0 + 8) * N + col], W[(size_t)(k0 + 9) * N + col]);
    pW[id] = v;
}

__global__ void pack_all_kernel(const float* __restrict__ Wm1, const float* __restrict__ Wm2,
                                const float* __restrict__ Wn1, const float* __restrict__ Wn2)
{
    const int n1 =  8 * 32 * 32;
    const int n2 = 16 * 16 * 32;
    const int n3 = 16 * 32 * 32;
    const int n4 = 16 * 16 * 32;
    int id = blockIdx.x * 256 + threadIdx.x;
    if (id < n1)                     pack_one(Wm1, g_pWm1, id,                32, H);
    else if (id < n1 + n2)           pack_one(Wm2, g_pWm2, id - n1,           16, D);
    else if (id < n1 + n2 + n3)      pack_one(Wn1, g_pWn1, id - n1 - n2,      32, H);
    else if (id < n1 + n2 + n3 + n4) pack_one(Wn2, g_pWn2, id - n1 - n2 - n3, 16, D);
}

// 4-stage, distance-3 B-fragment pipeline (KT % 4 == 0)
#define B_PIPE_PROLOGUE(pW, g0, NG)                                            \
    uint2 bb[4][4];                                                            \
    _Pragma("unroll")                                                          \
    for (int s = 0; s < 3; ++s)                                                \
        _Pragma("unroll")                                                      \
        for (int ct = 0; ct < 4; ++ct)                                         \
            bb[s][ct] = pW[(size_t)(s * NG + g0 + ct) * 32 + lane];

#define B_PIPE_PREFETCH(pW, g0, NG, KT, k, j)                                  \
    if ((k) + 3 < (KT)) {                                                      \
        _Pragma("unroll")                                                      \
        for (int ct = 0; ct < 4; ++ct)                                         \
            bb[((j) + 3) & 3][ct] =                                            \
                pW[(size_t)(((k) + 3) * NG + g0 + ct) * 32 + lane];            \
    }

// ---------------------------------------------------------------------------
// Kernel 1: m = relu(X @ Wm1 + bm1) @ Wm2 + bm2   + zero g_agg rows
//   64-row tiles, 256 threads (8 warps), 2 CTAs/SM.
// ---------------------------------------------------------------------------
__global__ __launch_bounds__(256, 2)
void msg_mlp_kernel(const float* __restrict__ nodes,
                    const float* __restrict__ bm1, const float* __restrict__ bm2)
{
    extern __shared__ __half smemh[];
    __half* sX = smemh;                     // [64][LDXh] fp16
    __half* sH = smemh + TILE_M * LDXh;     // [64][LDHh] fp16

    const int row0 = blockIdx.x * TILE_M;
    const int tid  = threadIdx.x;
    const int warp = tid >> 5;
    const int lane = tid & 31;
    const int lq   = lane >> 2;
    const int lr   = lane & 3;

    // zero this tile's g_agg rows
    for (int i = tid; i < TILE_M * (D / 4); i += 256) {
        int r  = i >> 5;
        int c4 = (i & 31) * 4;
        int gr = row0 + r;
        if (gr < N_NODES)
            *reinterpret_cast<float4*>(g_agg + (size_t)gr * D + c4) =
                make_float4(0.f, 0.f, 0.f, 0.f);
    }

    // stage X tile (fp32 -> fp16)
    for (int i = tid; i < TILE_M * (D / 4); i += 256) {
        int r  = i >> 5;
        int c4 = (i & 31) * 4;
        float4 v = make_float4(0.f, 0.f, 0.f, 0.f);
        int gr = row0 + r;
        if (gr < N_NODES) v = *reinterpret_cast<const float4*>(nodes + (size_t)gr * D + c4);
        *reinterpret_cast<uint2*>(sX + r * LDXh + c4) =
            make_uint2(f2h2(v.x, v.y), f2h2(v.z, v.w));
    }
    __syncthreads();

    // ---- GEMM1: hidden[64x256] = relu(X @ Wm1 + bm1); warp owns 32 cols
    {
        const int g0 = warp * 4;
        const int KT = D / 16;              // 8
        const int NG = H / 8;               // 32

        float acc[4][4][4];
        #pragma unroll
        for (int i = 0; i < 4; ++i)
            #pragma unroll
            for (int j = 0; j < 4; ++j)
                #pragma unroll
                for (int k = 0; k < 4; ++k) acc[i][j][k] = 0.f;

        const uint32_t abase = ldsm_base(sX, LDXh, lane);

        B_PIPE_PROLOGUE(g_pWm1, g0, NG)

        #pragma unroll 1
        for (int kt = 0; kt < KT; kt += 4) {
            #pragma unroll
            for (int j = 0; j < 4; ++j) {
                const int k = kt + j;
                B_PIPE_PREFETCH(g_pWm1, g0, NG, KT, k, j)
                const int kb = k * 16;
                #pragma unroll
                for (int rt = 0; rt < 4; ++rt) {
                    uint32_t a[4];
                    ldsm_x4(a, abase + ((uint32_t)(rt * 16 * LDXh + kb) << 1));
                    #pragma unroll
                    for (int ct = 0; ct < 4; ++ct)
                        mma_f16(acc[rt][ct], a, reinterpret_cast<const uint32_t*>(&bb[j][ct]));
                }
            }
        }
        // bias + relu -> sH (fp16)
        #pragma unroll
        for (int rt = 0; rt < 4; ++rt) {
            #pragma unroll
            for (int ct = 0; ct < 4; ++ct) {
                int r = rt * 16 + lq;
                int c = warp * 32 + ct * 8 + lr * 2;
                float b0 = __ldg(bm1 + c), b1 = __ldg(bm1 + c + 1);
                *reinterpret_cast<uint32_t*>(sH + r * LDHh + c) =
                    f2h2(fmaxf(acc[rt][ct][0] + b0, 0.f), fmaxf(acc[rt][ct][1] + b1, 0.f));
                *reinterpret_cast<uint32_t*>(sH + (r + 8) * LDHh + c) =
                    f2h2(fmaxf(acc[rt][ct][2] + b0, 0.f), fmaxf(acc[rt][ct][3] + b1, 0.f));
            }
        }
    }
    __syncthreads();

    // ---- GEMM2: m[64x128] = hidden @ Wm2 + bm2  (stored fp16)
    {
        const int wr = warp >> 2;           // 0..1 -> rows wr*32
        const int wc = warp & 3;            // 0..3 -> cols wc*32
        const int g0 = wc * 4;
        const int KT = H / 16;              // 16
        const int NG = D / 8;               // 16

        float acc[2][4][4];
        #pragma unroll
        for (int i = 0; i < 2; ++i)
            #pragma unroll
            for (int j = 0; j < 4; ++j)
                #pragma unroll
                for (int k = 0; k < 4; ++k) acc[i][j][k] = 0.f;

        const uint32_t abase = ldsm_base(sH, LDHh, lane) +
                               ((uint32_t)(wr * 32 * LDHh) << 1);

        B_PIPE_PROLOGUE(g_pWm2, g0, NG)

        #pragma unroll 1
        for (int kt = 0; kt < KT; kt += 4) {
            #pragma unroll
            for (int j = 0; j < 4; ++j) {
                const int k = kt + j;
                B_PIPE_PREFETCH(g_pWm2, g0, NG, KT, k, j)
                const int kb = k * 16;
                #pragma unroll
                for (int rt = 0; rt < 2; ++rt) {
                    uint32_t a[4];
                    ldsm_x4(a, abase + ((uint32_t)(rt * 16 * LDHh + kb) << 1));
                    #pragma unroll
                    for (int ct = 0; ct < 4; ++ct)
                        mma_f16(acc[rt][ct], a, reinterpret_cast<const uint32_t*>(&bb[j][ct]));
                }
            }
        }
        #pragma unroll
        for (int rt = 0; rt < 2; ++rt) {
            #pragma unroll
            for (int ct = 0; ct < 4; ++ct) {
                int r = wr * 32 + rt * 16 + lq;
                int c = wc * 32 + ct * 8 + lr * 2;
                float b0 = __ldg(bm2 + c), b1 = __ldg(bm2 + c + 1);
                int gr = row0 + r;
                if (gr < N_NODES)
                    *reinterpret_cast<uint32_t*>(g_m + (size_t)gr * D + c) =
                        f2h2(acc[rt][ct][0] + b0, acc[rt][ct][1] + b1);
                int gr2 = gr + 8;
                if (gr2 < N_NODES)
                    *reinterpret_cast<uint32_t*>(g_m + (size_t)gr2 * D + c) =
                        f2h2(acc[rt][ct][2] + b0, acc[rt][ct][3] + b1);
            }
        }
    }
}

// ---------------------------------------------------------------------------
// Kernel 2: agg[recv] += m[send]   (one warp per edge; fp16 read, f32 RED)
// ---------------------------------------------------------------------------
__global__ __launch_bounds__(256)
void scatter_kernel(const int* __restrict__ senders, const int* __restrict__ receivers)
{
    int e = (blockIdx.x * 256 + threadIdx.x) >> 5;
    int lane = threadIdx.x & 31;
    if (e >= N_EDGES) return;
    int s = __ldg(senders + e);
    int r = __ldg(receivers + e);
    uint2 mm = *reinterpret_cast<const uint2*>(g_m + (size_t)s * D + lane * 4);
    __half2 h01 = *reinterpret_cast<__half2*>(&mm.x);
    __half2 h23 = *reinterpret_cast<__half2*>(&mm.y);
    float2 f01 = __half22float2(h01);
    float2 f23 = __half22float2(h23);
    float* dst = g_agg + (size_t)r * D + lane * 4;
    asm volatile("red.global.add.v4.f32 [%0], {%1,%2,%3,%4};"
                 :: "l"(dst), "f"(f01.x), "f"(f01.y), "f"(f23.x), "f"(f23.y)
                 : "memory");
}

// ---------------------------------------------------------------------------
// Kernel 3: out = nodes + relu([nodes||agg] @ Wn1 + bn1) @ Wn2 + bn2
//   64-row tiles, 256 threads, 2 CTAs/SM.
// ---------------------------------------------------------------------------
__global__ __launch_bounds__(256, 2)
void node_mlp_kernel(const float* __restrict__ nodes,
                     const float* __restrict__ bn1, const float* __restrict__ bn2,
                     float* __restrict__ out)
{
    extern __shared__ __half smemh[];
    __half* sA = smemh;   // [64][LDHh]; A = [X||agg], later reused as hidden

    const int row0 = blockIdx.x * TILE_M;
    const int tid  = threadIdx.x;
    const int warp = tid >> 5;
    const int lane = tid & 31;
    const int lq   = lane >> 2;
    const int lr   = lane & 3;

    // stage A = [nodes || agg], 64 x 256, fp16
    for (int i = tid; i < TILE_M * (2 * D / 4); i += 256) {
        int r  = i >> 6;
        int c4 = (i & 63) * 4;
        float4 v = make_float4(0.f, 0.f, 0.f, 0.f);
        int gr = row0 + r;
        if (gr < N_NODES) {
            if (c4 < D) v = *reinterpret_cast<const float4*>(nodes + (size_t)gr * D + c4);
            else        v = *reinterpret_cast<const float4*>(g_agg + (size_t)gr * D + (c4 - D));
        }
        *reinterpret_cast<uint2*>(sA + r * LDHh + c4) =
            make_uint2(f2h2(v.x, v.y), f2h2(v.z, v.w));
    }
    __syncthreads();

    // ---- GEMM1: hidden[64x256] = relu(A @ Wn1 + bn1); warp owns 32 cols
    float acc1[4][4][4];
    #pragma unroll
    for (int i = 0; i < 4; ++i)
        #pragma unroll
        for (int j = 0; j < 4; ++j)
            #pragma unroll
            for (int k = 0; k < 4; ++k) acc1[i][j][k] = 0.f;

    {
        const int g0 = warp * 4;
        const int KT = (2 * D) / 16;        // 16
        const int NG = H / 8;               // 32

        const uint32_t abase = ldsm_base(sA, LDHh, lane);

        B_PIPE_PROLOGUE(g_pWn1, g0, NG)

        #pragma unroll 1
        for (int kt = 0; kt < KT; kt += 4) {
            #pragma unroll
            for (int j = 0; j < 4; ++j) {
                const int k = kt + j;
                B_PIPE_PREFETCH(g_pWn1, g0, NG, KT, k, j)
                const int kb = k * 16;
                #pragma unroll
                for (int rt = 0; rt < 4; ++rt) {
                    uint32_t a[4];
                    ldsm_x4(a, abase + ((uint32_t)(rt * 16 * LDHh + kb) << 1));
                    #pragma unroll
                    for (int ct = 0; ct < 4; ++ct)
                        mma_f16(acc1[rt][ct], a, reinterpret_cast<const uint32_t*>(&bb[j][ct]));
                }
            }
        }
    }
    __syncthreads();   // all warps done READING sA

    // write hidden (bias + relu, fp16) over sA
    #pragma unroll
    for (int rt = 0; rt < 4; ++rt) {
        #pragma unroll
        for (int ct = 0; ct < 4; ++ct) {
            int r = rt * 16 + lq;
            int c = warp * 32 + ct * 8 + lr * 2;
            float b0 = __ldg(bn1 + c), b1 = __ldg(bn1 + c + 1);
            *reinterpret_cast<uint32_t*>(sA + r * LDHh + c) =
                f2h2(fmaxf(acc1[rt][ct][0] + b0, 0.f), fmaxf(acc1[rt][ct][1] + b1, 0.f));
            *reinterpret_cast<uint32_t*>(sA + (r + 8) * LDHh + c) =
                f2h2(fmaxf(acc1[rt][ct][2] + b0, 0.f), fmaxf(acc1[rt][ct][3] + b1, 0.f));
        }
    }
    __syncthreads();

    // ---- GEMM2: out = nodes + hidden @ Wn2 + bn2
    {
        const int wr = warp >> 2;           // 0..1
        const int wc = warp & 3;            // 0..3
        const int g0 = wc * 4;
        const int KT = H / 16;              // 16
        const int NG = D / 8;               // 16

        float acc[2][4][4];
        #pragma unroll
        for (int i = 0; i < 2; ++i)
            #pragma unroll
            for (int j = 0; j < 4; ++j)
                #pragma unroll
                for (int k = 0; k < 4; ++k) acc[i][j][k] = 0.f;

        const uint32_t abase = ldsm_base(sA, LDHh, lane) +
                               ((uint32_t)(wr * 32 * LDHh) << 1);

        B_PIPE_PROLOGUE(g_pWn2, g0, NG)

        #pragma unroll 1
        for (int kt = 0; kt < KT; kt += 4) {
            #pragma unroll
            for (int j = 0; j < 4; ++j) {
                const int k = kt + j;
                B_PIPE_PREFETCH(g_pWn2, g0, NG, KT, k, j)
                const int kb = k * 16;
                #pragma unroll
                for (int rt = 0; rt < 2; ++rt) {
                    uint32_t a[4];
                    ldsm_x4(a, abase + ((uint32_t)(rt * 16 * LDHh + kb) << 1));
                    #pragma unroll
                    for (int ct = 0; ct < 4; ++ct)
                        mma_f16(acc[rt][ct], a, reinterpret_cast<const uint32_t*>(&bb[j][ct]));
                }
            }
        }
        #pragma unroll
        for (int rt = 0; rt < 2; ++rt) {
            #pragma unroll
            for (int ct = 0; ct < 4; ++ct) {
                int r = wr * 32 + rt * 16 + lq;
                int c = wc * 32 + ct * 8 + lr * 2;
                float b0 = __ldg(bn2 + c), b1 = __ldg(bn2 + c + 1);
                int gr = row0 + r;
                if (gr < N_NODES) {
                    float2 xn = *reinterpret_cast<const float2*>(nodes + (size_t)gr * D + c);
                    float2 v  = make_float2(xn.x + acc[rt][ct][0] + b0,
                                            xn.y + acc[rt][ct][1] + b1);
                    *reinterpret_cast<float2*>(out + (size_t)gr * D + c) = v;
                }
                int gr2 = gr + 8;
                if (gr2 < N_NODES) {
                    float2 xn = *reinterpret_cast<const float2*>(nodes + (size_t)gr2 * D + c);
                    float2 v  = make_float2(xn.x + acc[rt][ct][2] + b0,
                                            xn.y + acc[rt][ct][3] + b1);
                    *reinterpret_cast<float2*>(out + (size_t)gr2 * D + c) = v;
                }
            }
        }
    }
}

// ---------------------------------------------------------------------------
// launch
// ---------------------------------------------------------------------------
extern "C" void kernel_launch(void* const* d_in, const int* in_sizes, int n_in,
                              void* d_out, int out_size)
{
    const float* nodes     = (const float*)d_in[0];
    const int*   senders   = (const int*)  d_in[1];
    const int*   receivers = (const int*)  d_in[2];
    const float* Wm1 = (const float*)d_in[3];
    const float* bm1 = (const float*)d_in[4];
    const float* Wm2 = (const float*)d_in[5];
    const float* bm2 = (const float*)d_in[6];
    const float* Wn1 = (const float*)d_in[7];
    const float* bn1 = (const float*)d_in[8];
    const float* Wn2 = (const float*)d_in[9];
    const float* bn2 = (const float*)d_in[10];
    float* out = (float*)d_out;

    const int SMEM1 = (TILE_M * LDXh + TILE_M * LDHh) * 2;   // 51200 B -> 2 CTA/SM
    const int SMEM3 = (TILE_M * LDHh) * 2;                   // 33792 B -> 2 CTA/SM
    cudaFuncSetAttribute(msg_mlp_kernel,  cudaFuncAttributeMaxDynamicSharedMemorySize, SMEM1);
    cudaFuncSetAttribute(node_mlp_kernel, cudaFuncAttributeMaxDynamicSharedMemorySize, SMEM3);

    // pack all weights in one launch
    {
        int n = 8*32*32 + 16*16*32 + 16*32*32 + 16*16*32;   // 40960
        pack_all_kernel<<<(n + 255) / 256, 256>>>(Wm1, Wm2, Wn1, Wn2);
    }

    // m = MLP1(nodes); also zeroes g_agg per tile
    msg_mlp_kernel<<<NTILES, 256, SMEM1>>>(nodes, bm1, bm2);

    // agg[recv] += m[send]
    {
        long long threads = (long long)N_EDGES * 32;
        int blocks = (int)((threads + 255) / 256);
        scatter_kernel<<<blocks, 256>>>(senders, receivers);
    }

    // out = nodes + MLP2([nodes||agg])
    node_mlp_kernel<<<NTILES, 256, SMEM3>>>(nodes, bn1, bn2, out);
}

// round 17
// speedup vs baseline: 2.3287x; 1.0843x over previous
#include <cuda_runtime.h>
#include <cuda_fp16.h>
#include <stdint.h>

#define N_NODES 100000
#define N_EDGES 600000
#define D 128
#define H 256
#define TILE_M 32
#define NTILES ((N_NODES + TILE_M - 1) / TILE_M)   // 3125 (exact)

#define LDXh 136   // smem row stride (halves), 128-col tile
#define LDHh 264   // smem row stride (halves), 256-col tile

// Scratch (allocation-free rule: device globals)
__device__ __half g_m[(size_t)N_NODES * D];
__device__ float  g_agg[(size_t)N_NODES * D];

// Pre-packed fp16 weights in m16n8k16-fragment order (see pack_one)
__device__ uint2 g_pWm1[ 8 * 32 * 32];   // Wm1: KT=8,  NG=32
__device__ uint2 g_pWm2[16 * 16 * 32];   // Wm2: KT=16, NG=16
__device__ uint2 g_pWn1[16 * 32 * 32];   // Wn1: KT=16, NG=32
__device__ uint2 g_pWn2[16 * 16 * 32];   // Wn2: KT=16, NG=16

// ---------------------------------------------------------------------------
// helpers
// ---------------------------------------------------------------------------
__device__ __forceinline__ uint32_t f2h2(float lo, float hi) {
    __half2 h = __floats2half2_rn(lo, hi);
    return *reinterpret_cast<uint32_t*>(&h);
}

__device__ __forceinline__ void mma_f16(float c[4], const uint32_t a[4], const uint32_t* b) {
    asm volatile(
        "mma.sync.aligned.m16n8k16.row.col.f32.f16.f16.f32 "
        "{%0,%1,%2,%3}, {%4,%5,%6,%7}, {%8,%9}, {%0,%1,%2,%3};\n"
        : "+f"(c[0]), "+f"(c[1]), "+f"(c[2]), "+f"(c[3])
        : "r"(a[0]), "r"(a[1]), "r"(a[2]), "r"(a[3]),
          "r"(b[0]), "r"(b[1]));
}

// One ldmatrix.x4 loads the full m16n8k16 A fragment (4x 8x8 b16 tiles).
__device__ __forceinline__ void ldsm_x4(uint32_t a[4], uint32_t addr) {
    asm volatile(
        "ldmatrix.sync.aligned.m8n8.x4.shared.b16 {%0,%1,%2,%3}, [%4];"
        : "=r"(a[0]), "=r"(a[1]), "=r"(a[2]), "=r"(a[3]) : "r"(addr));
}

// Per-lane base for ldmatrix over a row-major [rows][ld] half tile.
__device__ __forceinline__ uint32_t ldsm_base(const __half* s, int ld, int lane) {
    uint32_t u = (uint32_t)__cvta_generic_to_shared(s);
    return u + ((uint32_t)((lane & 15) * ld + ((lane >> 4) << 3)) << 1);
}

// ---------------------------------------------------------------------------
// One fused pack kernel: all four weight matrices -> fragment-ordered fp16
// ---------------------------------------------------------------------------
__device__ __forceinline__ void pack_one(const float* __restrict__ W,
                                         uint2* __restrict__ pW,
                                         int id, int Ng, int N)
{
    int lane = id & 31;
    int g    = (id >> 5) % Ng;
    int kt   = (id >> 5) / Ng;
    int lr = lane & 3, lq = lane >> 2;
    int col = g * 8 + lq;
    int k0 = kt * 16 + lr * 2;
    uint2 v;
    v.x = f2h2(W[(size_t)k0       * N + col], W[(size_t)(k0 + 1) * N + col]);
    v.y = f2h2(W[(size_t)(k0 + 8) * N + col], W[(size_t)(k0 + 9) * N + col]);
    pW[id] = v;
}

__global__ void pack_all_kernel(const float* __restrict__ Wm1, const float* __restrict__ Wm2,
                                const float* __restrict__ Wn1, const float* __restrict__ Wn2)
{
    const int n1 =  8 * 32 * 32;
    const int n2 = 16 * 16 * 32;
    const int n3 = 16 * 32 * 32;
    const int n4 = 16 * 16 * 32;
    int id = blockIdx.x * 256 + threadIdx.x;
    if (id < n1)                     pack_one(Wm1, g_pWm1, id,                32, H);
    else if (id < n1 + n2)           pack_one(Wm2, g_pWm2, id - n1,           16, D);
    else if (id < n1 + n2 + n3)      pack_one(Wn1, g_pWn1, id - n1 - n2,      32, H);
    else if (id < n1 + n2 + n3 + n4) pack_one(Wn2, g_pWn2, id - n1 - n2 - n3, 16, D);
}

// 4-stage, distance-3 B-fragment pipeline (KT % 4 == 0)
#define B_PIPE_PROLOGUE(pW, g0, NG)                                            \
    uint2 bb[4][4];                                                            \
    _Pragma("unroll")                                                          \
    for (int s = 0; s < 3; ++s)                                                \
        _Pragma("unroll")                                                      \
        for (int ct = 0; ct < 4; ++ct)                                         \
            bb[s][ct] = pW[(size_t)(s * NG + g0 + ct) * 32 + lane];

#define B_PIPE_PREFETCH(pW, g0, NG, KT, k, j)                                  \
    if ((k) + 3 < (KT)) {                                                      \
        _Pragma("unroll")                                                      \
        for (int ct = 0; ct < 4; ++ct)                                         \
            bb[((j) + 3) & 3][ct] =                                            \
                pW[(size_t)(((k) + 3) * NG + g0 + ct) * 32 + lane];            \
    }

// ---------------------------------------------------------------------------
// Kernel 1: m = relu(X @ Wm1 + bm1) @ Wm2 + bm2   + zero g_agg rows
//   32-row tiles, 256 threads (8 warps), 3 CTAs/SM.
//   GEMM1: all warps rows 0-31, warp owns 32 cols (rt=2, ct=4)
//   GEMM2: warp grid 2x4, warp tile 16x32 (rt=1, ct=4)
// ---------------------------------------------------------------------------
__global__ __launch_bounds__(256, 3)
void msg_mlp_kernel(const float* __restrict__ nodes,
                    const float* __restrict__ bm1, const float* __restrict__ bm2)
{
    extern __shared__ __half smemh[];
    __half* sX = smemh;                     // [32][LDXh] fp16
    __half* sH = smemh + TILE_M * LDXh;     // [32][LDHh] fp16

    const int row0 = blockIdx.x * TILE_M;
    const int tid  = threadIdx.x;
    const int warp = tid >> 5;
    const int lane = tid & 31;
    const int lq   = lane >> 2;
    const int lr   = lane & 3;

    // zero this tile's g_agg rows
    for (int i = tid; i < TILE_M * (D / 4); i += 256) {
        int r  = i >> 5;
        int c4 = (i & 31) * 4;
        int gr = row0 + r;
        if (gr < N_NODES)
            *reinterpret_cast<float4*>(g_agg + (size_t)gr * D + c4) =
                make_float4(0.f, 0.f, 0.f, 0.f);
    }

    // stage X tile (fp32 -> fp16)
    for (int i = tid; i < TILE_M * (D / 4); i += 256) {
        int r  = i >> 5;
        int c4 = (i & 31) * 4;
        float4 v = make_float4(0.f, 0.f, 0.f, 0.f);
        int gr = row0 + r;
        if (gr < N_NODES) v = *reinterpret_cast<const float4*>(nodes + (size_t)gr * D + c4);
        *reinterpret_cast<uint2*>(sX + r * LDXh + c4) =
            make_uint2(f2h2(v.x, v.y), f2h2(v.z, v.w));
    }
    __syncthreads();

    // ---- GEMM1: hidden[32x256] = relu(X @ Wm1 + bm1); warp owns 32 cols
    {
        const int g0 = warp * 4;
        const int KT = D / 16;              // 8
        const int NG = H / 8;               // 32

        float acc[2][4][4];
        #pragma unroll
        for (int i = 0; i < 2; ++i)
            #pragma unroll
            for (int j = 0; j < 4; ++j)
                #pragma unroll
                for (int k = 0; k < 4; ++k) acc[i][j][k] = 0.f;

        const uint32_t abase = ldsm_base(sX, LDXh, lane);

        B_PIPE_PROLOGUE(g_pWm1, g0, NG)

        #pragma unroll 1
        for (int kt = 0; kt < KT; kt += 4) {
            #pragma unroll
            for (int j = 0; j < 4; ++j) {
                const int k = kt + j;
                B_PIPE_PREFETCH(g_pWm1, g0, NG, KT, k, j)
                const int kb = k * 16;
                #pragma unroll
                for (int rt = 0; rt < 2; ++rt) {
                    uint32_t a[4];
                    ldsm_x4(a, abase + ((uint32_t)(rt * 16 * LDXh + kb) << 1));
                    #pragma unroll
                    for (int ct = 0; ct < 4; ++ct)
                        mma_f16(acc[rt][ct], a, reinterpret_cast<const uint32_t*>(&bb[j][ct]));
                }
            }
        }
        // bias + relu -> sH (fp16)
        #pragma unroll
        for (int rt = 0; rt < 2; ++rt) {
            #pragma unroll
            for (int ct = 0; ct < 4; ++ct) {
                int r = rt * 16 + lq;
                int c = warp * 32 + ct * 8 + lr * 2;
                float b0 = __ldg(bm1 + c), b1 = __ldg(bm1 + c + 1);
                *reinterpret_cast<uint32_t*>(sH + r * LDHh + c) =
                    f2h2(fmaxf(acc[rt][ct][0] + b0, 0.f), fmaxf(acc[rt][ct][1] + b1, 0.f));
                *reinterpret_cast<uint32_t*>(sH + (r + 8) * LDHh + c) =
                    f2h2(fmaxf(acc[rt][ct][2] + b0, 0.f), fmaxf(acc[rt][ct][3] + b1, 0.f));
            }
        }
    }
    __syncthreads();

    // ---- GEMM2: m[32x128] = hidden @ Wm2 + bm2  (stored fp16)
    {
        const int wr = warp >> 2;           // 0..1 -> rows wr*16
        const int wc = warp & 3;            // 0..3 -> cols wc*32
        const int g0 = wc * 4;
        const int KT = H / 16;              // 16
        const int NG = D / 8;               // 16

        float acc[4][4];
        #pragma unroll
        for (int j = 0; j < 4; ++j)
            #pragma unroll
            for (int k = 0; k < 4; ++k) acc[j][k] = 0.f;

        const uint32_t abase = ldsm_base(sH, LDHh, lane) +
                               ((uint32_t)(wr * 16 * LDHh) << 1);

        B_PIPE_PROLOGUE(g_pWm2, g0, NG)

        #pragma unroll 1
        for (int kt = 0; kt < KT; kt += 4) {
            #pragma unroll
            for (int j = 0; j < 4; ++j) {
                const int k = kt + j;
                B_PIPE_PREFETCH(g_pWm2, g0, NG, KT, k, j)
                const int kb = k * 16;
                uint32_t a[4];
                ldsm_x4(a, abase + ((uint32_t)kb << 1));
                #pragma unroll
                for (int ct = 0; ct < 4; ++ct)
                    mma_f16(acc[ct], a, reinterpret_cast<const uint32_t*>(&bb[j][ct]));
            }
        }
        #pragma unroll
        for (int ct = 0; ct < 4; ++ct) {
            int r = wr * 16 + lq;
            int c = wc * 32 + ct * 8 + lr * 2;
            float b0 = __ldg(bm2 + c), b1 = __ldg(bm2 + c + 1);
            int gr = row0 + r;
            if (gr < N_NODES)
                *reinterpret_cast<uint32_t*>(g_m + (size_t)gr * D + c) =
                    f2h2(acc[ct][0] + b0, acc[ct][1] + b1);
            int gr2 = gr + 8;
            if (gr2 < N_NODES)
                *reinterpret_cast<uint32_t*>(g_m + (size_t)gr2 * D + c) =
                    f2h2(acc[ct][2] + b0, acc[ct][3] + b1);
        }
    }
}

// ---------------------------------------------------------------------------
// Kernel 2: agg[recv] += m[send]   (one warp per edge; fp16 read, f32 RED)
// ---------------------------------------------------------------------------
__global__ __launch_bounds__(256)
void scatter_kernel(const int* __restrict__ senders, const int* __restrict__ receivers)
{
    int e = (blockIdx.x * 256 + threadIdx.x) >> 5;
    int lane = threadIdx.x & 31;
    if (e >= N_EDGES) return;
    int s = __ldg(senders + e);
    int r = __ldg(receivers + e);
    uint2 mm = *reinterpret_cast<const uint2*>(g_m + (size_t)s * D + lane * 4);
    __half2 h01 = *reinterpret_cast<__half2*>(&mm.x);
    __half2 h23 = *reinterpret_cast<__half2*>(&mm.y);
    float2 f01 = __half22float2(h01);
    float2 f23 = __half22float2(h23);
    float* dst = g_agg + (size_t)r * D + lane * 4;
    asm volatile("red.global.add.v4.f32 [%0], {%1,%2,%3,%4};"
                 :: "l"(dst), "f"(f01.x), "f"(f01.y), "f"(f23.x), "f"(f23.y)
                 : "memory");
}

// ---------------------------------------------------------------------------
// Kernel 3: out = nodes + relu([nodes||agg] @ Wn1 + bn1) @ Wn2 + bn2
//   32-row tiles, 256 threads, 3 CTAs/SM.
// ---------------------------------------------------------------------------
__global__ __launch_bounds__(256, 3)
void node_mlp_kernel(const float* __restrict__ nodes,
                     const float* __restrict__ bn1, const float* __restrict__ bn2,
                     float* __restrict__ out)
{
    extern __shared__ __half smemh[];
    __half* sA = smemh;   // [32][LDHh]; A = [X||agg], later reused as hidden

    const int row0 = blockIdx.x * TILE_M;
    const int tid  = threadIdx.x;
    const int warp = tid >> 5;
    const int lane = tid & 31;
    const int lq   = lane >> 2;
    const int lr   = lane & 3;

    // stage A = [nodes || agg], 32 x 256, fp16
    for (int i = tid; i < TILE_M * (2 * D / 4); i += 256) {
        int r  = i >> 6;
        int c4 = (i & 63) * 4;
        float4 v = make_float4(0.f, 0.f, 0.f, 0.f);
        int gr = row0 + r;
        if (gr < N_NODES) {
            if (c4 < D) v = *reinterpret_cast<const float4*>(nodes + (size_t)gr * D + c4);
            else        v = *reinterpret_cast<const float4*>(g_agg + (size_t)gr * D + (c4 - D));
        }
        *reinterpret_cast<uint2*>(sA + r * LDHh + c4) =
            make_uint2(f2h2(v.x, v.y), f2h2(v.z, v.w));
    }
    __syncthreads();

    // ---- GEMM1: hidden[32x256] = relu(A @ Wn1 + bn1); warp owns 32 cols
    float acc1[2][4][4];
    #pragma unroll
    for (int i = 0; i < 2; ++i)
        #pragma unroll
        for (int j = 0; j < 4; ++j)
            #pragma unroll
            for (int k = 0; k < 4; ++k) acc1[i][j][k] = 0.f;

    {
        const int g0 = warp * 4;
        const int KT = (2 * D) / 16;        // 16
        const int NG = H / 8;               // 32

        const uint32_t abase = ldsm_base(sA, LDHh, lane);

        B_PIPE_PROLOGUE(g_pWn1, g0, NG)

        #pragma unroll 1
        for (int kt = 0; kt < KT; kt += 4) {
            #pragma unroll
            for (int j = 0; j < 4; ++j) {
                const int k = kt + j;
                B_PIPE_PREFETCH(g_pWn1, g0, NG, KT, k, j)
                const int kb = k * 16;
                #pragma unroll
                for (int rt = 0; rt < 2; ++rt) {
                    uint32_t a[4];
                    ldsm_x4(a, abase + ((uint32_t)(rt * 16 * LDHh + kb) << 1));
                    #pragma unroll
                    for (int ct = 0; ct < 4; ++ct)
                        mma_f16(acc1[rt][ct], a, reinterpret_cast<const uint32_t*>(&bb[j][ct]));
                }
            }
        }
    }
    __syncthreads();   // all warps done READING sA

    // write hidden (bias + relu, fp16) over sA
    #pragma unroll
    for (int rt = 0; rt < 2; ++rt) {
        #pragma unroll
        for (int ct = 0; ct < 4; ++ct) {
            int r = rt * 16 + lq;
            int c = warp * 32 + ct * 8 + lr * 2;
            float b0 = __ldg(bn1 + c), b1 = __ldg(bn1 + c + 1);
            *reinterpret_cast<uint32_t*>(sA + r * LDHh + c) =
                f2h2(fmaxf(acc1[rt][ct][0] + b0, 0.f), fmaxf(acc1[rt][ct][1] + b1, 0.f));
            *reinterpret_cast<uint32_t*>(sA + (r + 8) * LDHh + c) =
                f2h2(fmaxf(acc1[rt][ct][2] + b0, 0.f), fmaxf(acc1[rt][ct][3] + b1, 0.f));
        }
    }
    __syncthreads();

    // ---- GEMM2: out = nodes + hidden @ Wn2 + bn2
    {
        const int wr = warp >> 2;           // 0..1 -> rows wr*16
        const int wc = warp & 3;            // 0..3 -> cols wc*32
        const int g0 = wc * 4;
        const int KT = H / 16;              // 16
        const int NG = D / 8;               // 16

        float acc[4][4];
        #pragma unroll
        for (int j = 0; j < 4; ++j)
            #pragma unroll
            for (int k = 0; k < 4; ++k) acc[j][k] = 0.f;

        const uint32_t abase = ldsm_base(sA, LDHh, lane) +
                               ((uint32_t)(wr * 16 * LDHh) << 1);

        B_PIPE_PROLOGUE(g_pWn2, g0, NG)

        #pragma unroll 1
        for (int kt = 0; kt < KT; kt += 4) {
            #pragma unroll
            for (int j = 0; j < 4; ++j) {
                const int k = kt + j;
                B_PIPE_PREFETCH(g_pWn2, g0, NG, KT, k, j)
                const int kb = k * 16;
                uint32_t a[4];
                ldsm_x4(a, abase + ((uint32_t)kb << 1));
                #pragma unroll
                for (int ct = 0; ct < 4; ++ct)
                    mma_f16(acc[ct], a, reinterpret_cast<const uint32_t*>(&bb[j][ct]));
            }
        }
        #pragma unroll
        for (int ct = 0; ct < 4; ++ct) {
            int r = wr * 16 + lq;
            int c = wc * 32 + ct * 8 + lr * 2;
            float b0 = __ldg(bn2 + c), b1 = __ldg(bn2 + c + 1);
            int gr = row0 + r;
            if (gr < N_NODES) {
                float2 xn = *reinterpret_cast<const float2*>(nodes + (size_t)gr * D + c);
                float2 v  = make_float2(xn.x + acc[ct][0] + b0,
                                        xn.y + acc[ct][1] + b1);
                *reinterpret_cast<float2*>(out + (size_t)gr * D + c) = v;
            }
            int gr2 = gr + 8;
            if (gr2 < N_NODES) {
                float2 xn = *reinterpret_cast<const float2*>(nodes + (size_t)gr2 * D + c);
                float2 v  = make_float2(xn.x + acc[ct][2] + b0,
                                        xn.y + acc[ct][3] + b1);
                *reinterpret_cast<float2*>(out + (size_t)gr2 * D + c) = v;
            }
        }
    }
}

// ---------------------------------------------------------------------------
// launch
// ---------------------------------------------------------------------------
extern "C" void kernel_launch(void* const* d_in, const int* in_sizes, int n_in,
                              void* d_out, int out_size)
{
    const float* nodes     = (const float*)d_in[0];
    const int*   senders   = (const int*)  d_in[1];
    const int*   receivers = (const int*)  d_in[2];
    const float* Wm1 = (const float*)d_in[3];
    const float* bm1 = (const float*)d_in[4];
    const float* Wm2 = (const float*)d_in[5];
    const float* bm2 = (const float*)d_in[6];
    const float* Wn1 = (const float*)d_in[7];
    const float* bn1 = (const float*)d_in[8];
    const float* Wn2 = (const float*)d_in[9];
    const float* bn2 = (const float*)d_in[10];
    float* out = (float*)d_out;

    const int SMEM1 = (TILE_M * LDXh + TILE_M * LDHh) * 2;   // 25600 B -> 3 CTA/SM
    const int SMEM3 = (TILE_M * LDHh) * 2;                   // 16896 B -> 3 CTA/SM
    cudaFuncSetAttribute(msg_mlp_kernel,  cudaFuncAttributeMaxDynamicSharedMemorySize, SMEM1);
    cudaFuncSetAttribute(node_mlp_kernel, cudaFuncAttributeMaxDynamicSharedMemorySize, SMEM3);

    // pack all weights in one launch
    {
        int n = 8*32*32 + 16*16*32 + 16*32*32 + 16*16*32;   // 40960
        pack_all_kernel<<<(n + 255) / 256, 256>>>(Wm1, Wm2, Wn1, Wn2);
    }

    // m = MLP1(nodes); also zeroes g_agg per tile
    msg_mlp_kernel<<<NTILES, 256, SMEM1>>>(nodes, bm1, bm2);

    // agg[recv] += m[send]
    {
        long long threads = (long long)N_EDGES * 32;
        int blocks = (int)((threads + 255) / 256);
        scatter_kernel<<<blocks, 256>>>(senders, receivers);
    }

    // out = nodes + MLP2([nodes||agg])
    node_mlp_kernel<<<NTILES, 256, SMEM3>>>(nodes, bn1, bn2, out);
}